// round 7
// baseline (speedup 1.0000x reference)
#include <cuda_runtime.h>
#include <cuda_fp16.h>
#include <cstdint>
#include <cstddef>

// ===========================================================================
// DeepSDSphere R7: conv2 implicit-GEMM HMMA (2 output rows/block, rolling
// buffers), conv3 retiled 4px/thread, disco FFMA2 epilogue.
// ===========================================================================

#define B_   4
#define F_   64

typedef unsigned long long u64;

__device__ __forceinline__ u64 pack2(float lo, float hi) {
    u64 r;
    asm("mov.b64 %0, {%1, %2};" : "=l"(r) : "f"(lo), "f"(hi));
    return r;
}
__device__ __forceinline__ void fma2(u64& d, u64 a, u64 b) {
    asm("fma.rn.f32x2 %0, %1, %2, %0;" : "+l"(d) : "l"(a), "l"(b));
}
__device__ __forceinline__ float2 unpack2(u64 v) {
    float lo, hi;
    asm("mov.b64 {%0, %1}, %2;" : "=f"(lo), "=f"(hi) : "l"(v));
    return make_float2(lo, hi);
}
__device__ __forceinline__ uint32_t smem_u32(const void* p) {
    uint32_t a;
    asm("{ .reg .u64 t; cvta.to.shared.u64 t, %1; cvt.u32.u64 %0, t; }"
        : "=r"(a) : "l"(p));
    return a;
}

// ---------------- scratch layout (floats) -----------------------------------
#define SZ_NHWCH (4ull*364ull*724ull*64ull/2ull)
#define SZ_B2    (4ull*32ull*360ull*720ull)
#define SZ_H     (4ull*2ull*360ull*720ull)
#define SZ_Y1    (4ull*180ull*360ull)
#define SZ_WH    (25ull*64ull*32ull/2ull)
#define OFF_NHWCH 0ull
#define OFF_B2    (OFF_NHWCH + SZ_NHWCH)
#define OFF_H     (OFF_B2 + SZ_B2)
#define OFF_Y1    (OFF_H + SZ_H)
#define OFF_WH    (OFF_Y1 + SZ_Y1)
#define SCRATCH_FLOATS (OFF_WH + SZ_WH)

__device__ __align__(1024) float g_scratch[SCRATCH_FLOATS];

// ---------------------------------------------------------------------------
// bilinear 2x upsample + concat -> (B,2,H2,W2) NCHW fp32
// ---------------------------------------------------------------------------
__global__ void upsample_concat_kernel(const float* __restrict__ x,
                                       const float* __restrict__ elev,
                                       float* __restrict__ out,
                                       int Hin, int Win)
{
    int H2 = Hin * 2, W2 = Win * 2;
    int total = B_ * H2 * W2;
    int idx = blockIdx.x * blockDim.x + threadIdx.x;
    if (idx >= total) return;
    int j = idx % W2;
    int t = idx / W2;
    int i = t % H2;
    int b = t / H2;

    float sy = (i + 0.5f) * 0.5f - 0.5f;
    sy = fminf(fmaxf(sy, 0.0f), (float)(Hin - 1));
    int r0 = (int)floorf(sy);
    int r1 = min(r0 + 1, Hin - 1);
    float ty = sy - (float)r0;

    float sx = (j + 0.5f) * 0.5f - 0.5f;
    sx = fminf(fmaxf(sx, 0.0f), (float)(Win - 1));
    int c0 = (int)floorf(sx);
    int c1 = min(c0 + 1, Win - 1);
    float tx = sx - (float)c0;

    const float* xb = x + (size_t)b * Hin * Win;
    float v00 = xb[r0 * Win + c0];
    float v01 = xb[r0 * Win + c1];
    float v10 = xb[r1 * Win + c0];
    float v11 = xb[r1 * Win + c1];
    float left  = v00 * (1.0f - ty) + v10 * ty;
    float right = v01 * (1.0f - ty) + v11 * ty;
    float v = left * (1.0f - tx) + right * tx;

    size_t plane = (size_t)H2 * W2;
    out[((size_t)b * 2 + 0) * plane + (size_t)i * W2 + j] = v;
    out[((size_t)b * 2 + 1) * plane + (size_t)i * W2 + j] =
        elev[(size_t)b * plane + (size_t)i * W2 + j];
}

// ---------------------------------------------------------------------------
// zero 2-wide borders of padded NHWC fp16 buffer
// ---------------------------------------------------------------------------
__global__ void pad_zero_h_kernel(__half* __restrict__ nhwc, int Hp, int Wp)
{
    int i = blockIdx.x * 256 + threadIdx.x;
    int total = B_ * Hp * Wp;
    if (i >= total) return;
    int x = i % Wp;
    int y = (i / Wp) % Hp;
    if (y >= 2 && y < Hp - 2 && x >= 2 && x < Wp - 2) return;
    uint4 z = make_uint4(0, 0, 0, 0);
    uint4* p = (uint4*)(nhwc + (size_t)i * 64);
#pragma unroll
    for (int k = 0; k < 8; k++) p[k] = z;
}

// ---------------------------------------------------------------------------
// disco conv + bias + relu -> padded NHWC fp16.  FFMA2 oc-pair epilogue.
// ---------------------------------------------------------------------------
__global__ __launch_bounds__(256)
void disco_kernel(const float* __restrict__ h,
                  const int*   __restrict__ idx,
                  const float* __restrict__ val,
                  const float* __restrict__ w,
                  const float* __restrict__ bias,
                  __half* __restrict__ nhwc,
                  int P, int W, int Hp, int Wp)
{
    __shared__ __align__(8) float w_st[18][64];   // [c*9+k][oc]
    __shared__ __align__(8) float b_st[64];
    for (int t = threadIdx.x; t < 1152; t += 256) {
        int kk = t >> 6, o = t & 63;
        w_st[kk][o] = w[o * 18 + kk];
    }
    if (threadIdx.x < 64) b_st[threadIdx.x] = bias[threadIdx.x];
    __syncthreads();

    int p = blockIdx.x * 256 + threadIdx.x;
    if (p >= P) return;
    int px = p % W, py = p / W;

    int id[8];
    const int4* ip = reinterpret_cast<const int4*>(idx + (size_t)p * 8);
    int4 ia = ip[0], ib = ip[1];
    id[0]=ia.x; id[1]=ia.y; id[2]=ia.z; id[3]=ia.w;
    id[4]=ib.x; id[5]=ib.y; id[6]=ib.z; id[7]=ib.w;

    float v[9][8];
#pragma unroll
    for (int k = 0; k < 9; k++) {
        const float4* vp = reinterpret_cast<const float4*>(val + ((size_t)k * P + p) * 8);
        float4 a = vp[0], c = vp[1];
        v[k][0]=a.x; v[k][1]=a.y; v[k][2]=a.z; v[k][3]=a.w;
        v[k][4]=c.x; v[k][5]=c.y; v[k][6]=c.z; v[k][7]=c.w;
    }

    const u64* wp = (const u64*)&w_st[0][0];   // [kk][op], 32 u64 per kk
    const u64* bp = (const u64*)b_st;

    for (int b = 0; b < B_; b++) {
        const float* h0 = h + (size_t)(b * 2 + 0) * P;
        const float* h1 = h + (size_t)(b * 2 + 1) * P;
        float g0[8], g1[8];
#pragma unroll
        for (int n = 0; n < 8; n++) { g0[n] = h0[id[n]]; g1[n] = h1[id[n]]; }

        u64 zz[18];
#pragma unroll
        for (int k = 0; k < 9; k++) {
            float s0 = 0.0f, s1 = 0.0f;
#pragma unroll
            for (int n = 0; n < 8; n++) {
                s0 = fmaf(g0[n], v[k][n], s0);
                s1 = fmaf(g1[n], v[k][n], s1);
            }
            zz[k]     = pack2(s0, s0);
            zz[9 + k] = pack2(s1, s1);
        }

        uint4* ob = (uint4*)(nhwc +
            (((size_t)b * Hp + (py + 2)) * Wp + (px + 2)) * 64);
#pragma unroll
        for (int o8 = 0; o8 < 8; o8++) {
            __half hv[8];
#pragma unroll
            for (int q = 0; q < 4; q++) {
                int op = o8 * 4 + q;
                u64 a = bp[op];
#pragma unroll
                for (int kk = 0; kk < 18; kk++)
                    fma2(a, zz[kk], wp[kk * 32 + op]);
                float2 f = unpack2(a);
                hv[2 * q]     = __float2half_rn(fmaxf(f.x, 0.0f));
                hv[2 * q + 1] = __float2half_rn(fmaxf(f.y, 0.0f));
            }
            ob[o8] = *(uint4*)hv;
        }
    }
}

// ---------------------------------------------------------------------------
// weight transform: (32oc,64ic,5,5) fp32 -> fp16 [tap][ic][oc]
// ---------------------------------------------------------------------------
__global__ void wtransform_kernel(const float* __restrict__ w,
                                  __half* __restrict__ wh)
{
    int i = blockIdx.x * 256 + threadIdx.x;
    if (i >= 25 * 64 * 32) return;
    int tap = i / 2048;
    int r = i % 2048;
    int ic = r >> 5;
    int oc = r & 31;
    wh[i] = __float2half_rn(w[((size_t)oc * 64 + ic) * 25 + tap]);
}

// ---------------------------------------------------------------------------
// conv2 fp16 mma, 2 output rows per block with rolling A/B buffers.
// A row: 132px x 64ch fp16 swizzled = 16896 B (x2). B set: 5 taps x 64k x 80B
// = 25600 B (x2). dyn smem = 84992 B.
// ---------------------------------------------------------------------------
#define C2_SMEM 84992

__device__ __forceinline__ void mma_tap(float (&acc)[4][4], uint32_t Bbase,
                                        int dx, int ks, int lane,
                                        uint32_t a0, uint32_t a1,
                                        uint32_t a2, uint32_t a3)
{
#pragma unroll
    for (int j2 = 0; j2 < 2; j2++) {
        uint32_t b0, b1, b2, b3;
        int k = ks * 16 + (lane & 15);
        int g = j2 * 2 + (lane >> 4);
        uint32_t addr = Bbase + dx * 5120 + k * 80 + g * 16;
        asm volatile(
            "ldmatrix.sync.aligned.m8n8.x4.trans.shared.b16 {%0,%1,%2,%3}, [%4];"
            : "=r"(b0), "=r"(b1), "=r"(b2), "=r"(b3) : "r"(addr));
        float* d0 = acc[j2 * 2 + 0];
        asm volatile(
            "mma.sync.aligned.m16n8k16.row.col.f32.f16.f16.f32 "
            "{%0,%1,%2,%3}, {%4,%5,%6,%7}, {%8,%9}, {%0,%1,%2,%3};"
            : "+f"(d0[0]), "+f"(d0[1]), "+f"(d0[2]), "+f"(d0[3])
            : "r"(a0), "r"(a1), "r"(a2), "r"(a3), "r"(b0), "r"(b1));
        float* d1 = acc[j2 * 2 + 1];
        asm volatile(
            "mma.sync.aligned.m16n8k16.row.col.f32.f16.f16.f32 "
            "{%0,%1,%2,%3}, {%4,%5,%6,%7}, {%8,%9}, {%0,%1,%2,%3};"
            : "+f"(d1[0]), "+f"(d1[1]), "+f"(d1[2]), "+f"(d1[3])
            : "r"(a0), "r"(a1), "r"(a2), "r"(a3), "r"(b2), "r"(b3));
    }
}

__global__ __launch_bounds__(256)
void conv2_mma2(const __half* __restrict__ nhwc, const __half* __restrict__ wh,
                const float* __restrict__ bias, float* __restrict__ out,
                int H, int W)
{
    extern __shared__ __align__(16) char sm[];
    char* Ab0 = sm;
    char* Ab1 = sm + 16896;
    char* Bb0 = sm + 33792;
    char* Bb1 = sm + 59392;

    const int Hp = H + 4, Wp = W + 4;
    int b = blockIdx.z;
    int y0 = blockIdx.y * 2;
    int x0 = blockIdx.x * 128;
    if (x0 > W - 128) x0 = W - 128;
    int tid = threadIdx.x, warp = tid >> 5, lane = tid & 31;

    uint32_t Ab_b[2] = { smem_u32(Ab0), smem_u32(Ab1) };
    uint32_t Bb_b[2] = { smem_u32(Bb0), smem_u32(Bb1) };
    char* Ab[2] = { Ab0, Ab1 };
    char* Bb[2] = { Bb0, Bb1 };

    float acc0[4][4], acc1[4][4];
#pragma unroll
    for (int j = 0; j < 4; j++)
#pragma unroll
        for (int q = 0; q < 4; q++) { acc0[j][q] = 0.0f; acc1[j][q] = 0.0f; }

#pragma unroll
    for (int r = 0; r < 6; r++) {
        __syncthreads();
        // stage A source row y0 + r (padded coords)
        const uint4* srcA = (const uint4*)(nhwc +
            ((size_t)(b * Hp + y0 + r) * Wp + x0) * 64);
        char* A = Ab[r & 1];
        for (int i = tid; i < 1056; i += 256) {
            int p = i >> 3, g = i & 7;
            *(uint4*)(A + p * 128 + ((g ^ (p & 7)) << 4)) = srcA[i];
        }
        if (r < 5) {
            const uint4* srcB = (const uint4*)(wh + (size_t)r * 5 * 2048);
            char* Bd = Bb[r & 1];
            for (int i = tid; i < 1280; i += 256) {
                int t5 = i >> 8, k = (i >> 2) & 63, g = i & 3;
                *(uint4*)(Bd + t5 * 5120 + k * 80 + g * 16) = srcB[i];
            }
        }
        __syncthreads();

        uint32_t Abase = Ab_b[r & 1];
        uint32_t B0 = Bb_b[r & 1];        // tapset dy=r   (out row y0)
        uint32_t B1 = Bb_b[(r + 1) & 1];  // tapset dy=r-1 (out row y0+1)
#pragma unroll
        for (int dx = 0; dx < 5; dx++) {
#pragma unroll
            for (int ks = 0; ks < 4; ks++) {
                uint32_t a0, a1, a2, a3;
                int rr = warp * 16 + dx + (lane & 15);
                int g  = ks * 2 + (lane >> 4);
                uint32_t addr = Abase + rr * 128 + ((g ^ (rr & 7)) << 4);
                asm volatile(
                    "ldmatrix.sync.aligned.m8n8.x4.shared.b16 {%0,%1,%2,%3}, [%4];"
                    : "=r"(a0), "=r"(a1), "=r"(a2), "=r"(a3) : "r"(addr));
                if (r < 5)  mma_tap(acc0, B0, dx, ks, lane, a0, a1, a2, a3);
                if (r >= 1) mma_tap(acc1, B1, dx, ks, lane, a0, a1, a2, a3);
            }
        }
    }

    // epilogue: rows y0 and y0+1
    int r0 = lane >> 2, c0 = (lane & 3) * 2;
    int xbase = x0 + warp * 16;
#pragma unroll
    for (int j = 0; j < 4; j++) {
        int oc0 = j * 8 + c0;
        float bs0 = __ldg(&bias[oc0]), bs1 = __ldg(&bias[oc0 + 1]);
        size_t p0 = (((size_t)b * 32 + oc0)     * H + y0) * W;
        size_t p1 = (((size_t)b * 32 + oc0 + 1) * H + y0) * W;
        out[p0 + xbase + r0]     = fmaxf(acc0[j][0] + bs0, 0.0f);
        out[p1 + xbase + r0]     = fmaxf(acc0[j][1] + bs1, 0.0f);
        out[p0 + xbase + r0 + 8] = fmaxf(acc0[j][2] + bs0, 0.0f);
        out[p1 + xbase + r0 + 8] = fmaxf(acc0[j][3] + bs1, 0.0f);
        out[p0 + W + xbase + r0]     = fmaxf(acc1[j][0] + bs0, 0.0f);
        out[p1 + W + xbase + r0]     = fmaxf(acc1[j][1] + bs1, 0.0f);
        out[p0 + W + xbase + r0 + 8] = fmaxf(acc1[j][2] + bs0, 0.0f);
        out[p1 + W + xbase + r0 + 8] = fmaxf(acc1[j][3] + bs1, 0.0f);
    }
}

// ---------------------------------------------------------------------------
// conv3: 5x5, IC=32 -> OC=1. 128x8 px tile, 4 px/thread, register row-segments.
// ---------------------------------------------------------------------------
__global__ __launch_bounds__(256)
void conv3_kernel(const float* __restrict__ in, const float* __restrict__ w,
                  const float* __restrict__ bias, float* __restrict__ out,
                  int H, int W)
{
    const int ICC = 4, IC = 32;
    __shared__ __align__(16) float in_s[ICC][12][132];
    __shared__ float w_s[IC][25];

    int b  = blockIdx.z;
    int x0 = blockIdx.x * 128;
    int y0 = blockIdx.y * 8;
    int tid = threadIdx.x;
    int sx = tid & 31, sy = tid >> 5;

    for (int t = tid; t < IC * 25; t += 256) w_s[t / 25][t % 25] = w[t];

    float acc[4] = {0.f, 0.f, 0.f, 0.f};
    for (int cc = 0; cc < IC; cc += ICC) {
        __syncthreads();
        for (int t = tid; t < ICC * 12 * 132; t += 256) {
            int ic  = t / (12 * 132);
            int rem = t - ic * (12 * 132);
            int r = rem / 132, c = rem - r * 132;
            int gy = y0 - 2 + r, gx = x0 - 2 + c;
            float v = 0.f;
            if (gy >= 0 && gy < H && gx >= 0 && gx < W)
                v = in[((size_t)(b * IC + cc + ic) * H + gy) * W + gx];
            in_s[ic][r][c] = v;
        }
        __syncthreads();
#pragma unroll
        for (int ic = 0; ic < ICC; ic++) {
#pragma unroll
            for (int dy = 0; dy < 5; dy++) {
                const float* row = &in_s[ic][sy + dy][sx * 4];
                float4 Av = *(const float4*)row;
                float4 Bv = *(const float4*)(row + 4);
                float c8 = row[8];
                float v[9] = {Av.x, Av.y, Av.z, Av.w, Bv.x, Bv.y, Bv.z, Bv.w, c8};
                const float* wr = &w_s[cc + ic][dy * 5];
#pragma unroll
                for (int dx = 0; dx < 5; dx++) {
                    float wv = wr[dx];
#pragma unroll
                    for (int q = 0; q < 4; q++)
                        acc[q] = fmaf(v[dx + q], wv, acc[q]);
                }
            }
        }
    }

    int yy = y0 + sy;
    if (yy < H) {
#pragma unroll
        for (int q = 0; q < 4; q++) {
            int xx = x0 + sx * 4 + q;
            if (xx < W)
                out[((size_t)b * H + yy) * W + xx] = acc[q] + bias[0];
        }
    }
}

// ---------------------------------------------------------------------------
// Orchestration
// ---------------------------------------------------------------------------
extern "C" void kernel_launch(void* const* d_in, const int* in_sizes, int n_in,
                              void* d_out, int out_size)
{
    const float* x        = (const float*)d_in[0];
    const float* elev0    = (const float*)d_in[1];
    const float* elev1    = (const float*)d_in[2];
    const int*   psi_idx1 = (const int*)  d_in[3];
    const float* psi_val1 = (const float*)d_in[4];
    const float* w1       = (const float*)d_in[5];
    const float* b1       = (const float*)d_in[6];
    const float* cw2_1    = (const float*)d_in[7];
    const float* cb2_1    = (const float*)d_in[8];
    const float* cw3_1    = (const float*)d_in[9];
    const float* cb3_1    = (const float*)d_in[10];
    const int*   psi_idx2 = (const int*)  d_in[11];
    const float* psi_val2 = (const float*)d_in[12];
    const float* w2       = (const float*)d_in[13];
    const float* b2       = (const float*)d_in[14];
    const float* cw2_2    = (const float*)d_in[15];
    const float* cb2_2    = (const float*)d_in[16];
    const float* cw3_2    = (const float*)d_in[17];
    const float* cb3_2    = (const float*)d_in[18];
    float* out = (float*)d_out;

    float* scratch = nullptr;
    cudaGetSymbolAddress((void**)&scratch, g_scratch);
    __half* nhwcH = (__half*)(scratch + OFF_NHWCH);
    float*  bufB2 = scratch + OFF_B2;
    float*  bufH  = scratch + OFF_H;
    float*  bufY1 = scratch + OFF_Y1;
    __half* bufWH = (__half*)(scratch + OFF_WH);

    cudaFuncSetAttribute(conv2_mma2, cudaFuncAttributeMaxDynamicSharedMemorySize,
                         C2_SMEM);

    // ---------------- stage 1: 90x180 -> 180x360 ----------------
    {
        const int H = 180, W = 360, P = H * W, Hp = H + 4, Wp = W + 4;
        int total = B_ * H * W;
        upsample_concat_kernel<<<(total + 255) / 256, 256>>>(x, elev0, bufH, 90, 180);
        pad_zero_h_kernel<<<(B_ * Hp * Wp + 255) / 256, 256>>>(nhwcH, Hp, Wp);
        disco_kernel<<<(P + 255) / 256, 256>>>(bufH, psi_idx1, psi_val1, w1, b1,
                                               nhwcH, P, W, Hp, Wp);
        wtransform_kernel<<<200, 256>>>(cw2_1, bufWH);
        dim3 g2((W + 127) / 128, H / 2, B_);
        conv2_mma2<<<g2, 256, C2_SMEM>>>(nhwcH, bufWH, cb2_1, bufB2, H, W);
        dim3 g3((W + 127) / 128, (H + 7) / 8, B_);
        conv3_kernel<<<g3, 256>>>(bufB2, cw3_1, cb3_1, bufY1, H, W);
    }
    // ---------------- stage 2: 180x360 -> 360x720 ----------------
    {
        const int H = 360, W = 720, P = H * W, Hp = H + 4, Wp = W + 4;
        int total = B_ * H * W;
        upsample_concat_kernel<<<(total + 255) / 256, 256>>>(bufY1, elev1, bufH, 180, 360);
        pad_zero_h_kernel<<<(B_ * Hp * Wp + 255) / 256, 256>>>(nhwcH, Hp, Wp);
        disco_kernel<<<(P + 255) / 256, 256>>>(bufH, psi_idx2, psi_val2, w2, b2,
                                               nhwcH, P, W, Hp, Wp);
        wtransform_kernel<<<200, 256>>>(cw2_2, bufWH);
        dim3 g2((W + 127) / 128, H / 2, B_);
        conv2_mma2<<<g2, 256, C2_SMEM>>>(nhwcH, bufWH, cb2_2, bufB2, H, W);
        dim3 g3((W + 127) / 128, (H + 7) / 8, B_);
        conv3_kernel<<<g3, 256>>>(bufB2, cw3_2, cb3_2, out, H, W);
    }
}

// round 8
// speedup vs baseline: 2.0194x; 2.0194x over previous
#include <cuda_runtime.h>
#include <cuda_fp16.h>
#include <cstdint>
#include <cstddef>

// ===========================================================================
// DeepSDSphere R8: R6 (proven 1130us) + conv3 retiled 4px/thread ONLY.
// conv2 = exact R6 implicit-GEMM HMMA. disco = exact R6 scalar version.
// ===========================================================================

#define B_   4
#define F_   64

// ---------------- scratch layout (floats) -----------------------------------
#define SZ_NHWCH (4ull*364ull*724ull*64ull/2ull)   // fp16 NHWC as float count
#define SZ_B2    (4ull*32ull*360ull*720ull)
#define SZ_H     (4ull*2ull*360ull*720ull)
#define SZ_Y1    (4ull*180ull*360ull)
#define SZ_WH    (25ull*64ull*32ull/2ull)          // fp16 weights as float count
#define OFF_NHWCH 0ull
#define OFF_B2    (OFF_NHWCH + SZ_NHWCH)
#define OFF_H     (OFF_B2 + SZ_B2)
#define OFF_Y1    (OFF_H + SZ_H)
#define OFF_WH    (OFF_Y1 + SZ_Y1)
#define SCRATCH_FLOATS (OFF_WH + SZ_WH)

__device__ __align__(1024) float g_scratch[SCRATCH_FLOATS];

__device__ __forceinline__ uint32_t smem_u32(const void* p) {
    uint32_t a;
    asm("{ .reg .u64 t; cvta.to.shared.u64 t, %1; cvt.u32.u64 %0, t; }"
        : "=r"(a) : "l"(p));
    return a;
}

// ---------------------------------------------------------------------------
// bilinear 2x upsample (half-pixel) + concat -> (B,2,H2,W2) NCHW fp32
// ---------------------------------------------------------------------------
__global__ void upsample_concat_kernel(const float* __restrict__ x,
                                       const float* __restrict__ elev,
                                       float* __restrict__ out,
                                       int Hin, int Win)
{
    int H2 = Hin * 2, W2 = Win * 2;
    int total = B_ * H2 * W2;
    int idx = blockIdx.x * blockDim.x + threadIdx.x;
    if (idx >= total) return;
    int j = idx % W2;
    int t = idx / W2;
    int i = t % H2;
    int b = t / H2;

    float sy = (i + 0.5f) * 0.5f - 0.5f;
    sy = fminf(fmaxf(sy, 0.0f), (float)(Hin - 1));
    int r0 = (int)floorf(sy);
    int r1 = min(r0 + 1, Hin - 1);
    float ty = sy - (float)r0;

    float sx = (j + 0.5f) * 0.5f - 0.5f;
    sx = fminf(fmaxf(sx, 0.0f), (float)(Win - 1));
    int c0 = (int)floorf(sx);
    int c1 = min(c0 + 1, Win - 1);
    float tx = sx - (float)c0;

    const float* xb = x + (size_t)b * Hin * Win;
    float v00 = xb[r0 * Win + c0];
    float v01 = xb[r0 * Win + c1];
    float v10 = xb[r1 * Win + c0];
    float v11 = xb[r1 * Win + c1];
    float left  = v00 * (1.0f - ty) + v10 * ty;
    float right = v01 * (1.0f - ty) + v11 * ty;
    float v = left * (1.0f - tx) + right * tx;

    size_t plane = (size_t)H2 * W2;
    out[((size_t)b * 2 + 0) * plane + (size_t)i * W2 + j] = v;
    out[((size_t)b * 2 + 1) * plane + (size_t)i * W2 + j] =
        elev[(size_t)b * plane + (size_t)i * W2 + j];
}

// ---------------------------------------------------------------------------
// zero 2-wide borders of padded NHWC fp16 buffer (64ch/pixel = 128B)
// ---------------------------------------------------------------------------
__global__ void pad_zero_h_kernel(__half* __restrict__ nhwc, int Hp, int Wp)
{
    int i = blockIdx.x * 256 + threadIdx.x;
    int total = B_ * Hp * Wp;
    if (i >= total) return;
    int x = i % Wp;
    int y = (i / Wp) % Hp;
    if (y >= 2 && y < Hp - 2 && x >= 2 && x < Wp - 2) return;
    uint4 z = make_uint4(0, 0, 0, 0);
    uint4* p = (uint4*)(nhwc + (size_t)i * 64);
#pragma unroll
    for (int k = 0; k < 8; k++) p[k] = z;
}

// ---------------------------------------------------------------------------
// disco conv + bias + relu -> padded NHWC fp16 (exact R6 version)
// ---------------------------------------------------------------------------
__global__ __launch_bounds__(256)
void disco_kernel(const float* __restrict__ h,
                  const int*   __restrict__ idx,
                  const float* __restrict__ val,
                  const float* __restrict__ w,
                  const float* __restrict__ bias,
                  __half* __restrict__ nhwc,
                  int P, int W, int Hp, int Wp)
{
    __shared__ float w_s[F_ * 18];
    __shared__ float b_s[F_];
    for (int t = threadIdx.x; t < F_ * 18; t += 256) w_s[t] = w[t];
    if (threadIdx.x < F_) b_s[threadIdx.x] = bias[threadIdx.x];
    __syncthreads();

    int p = blockIdx.x * 256 + threadIdx.x;
    if (p >= P) return;
    int px = p % W, py = p / W;

    int id[8];
    const int4* ip = reinterpret_cast<const int4*>(idx + (size_t)p * 8);
    int4 ia = ip[0], ib = ip[1];
    id[0]=ia.x; id[1]=ia.y; id[2]=ia.z; id[3]=ia.w;
    id[4]=ib.x; id[5]=ib.y; id[6]=ib.z; id[7]=ib.w;

    float v[9][8];
#pragma unroll
    for (int k = 0; k < 9; k++) {
        const float4* vp = reinterpret_cast<const float4*>(val + ((size_t)k * P + p) * 8);
        float4 a = vp[0], c = vp[1];
        v[k][0]=a.x; v[k][1]=a.y; v[k][2]=a.z; v[k][3]=a.w;
        v[k][4]=c.x; v[k][5]=c.y; v[k][6]=c.z; v[k][7]=c.w;
    }

    for (int b = 0; b < B_; b++) {
        const float* h0 = h + (size_t)(b * 2 + 0) * P;
        const float* h1 = h + (size_t)(b * 2 + 1) * P;
        float g0[8], g1[8];
#pragma unroll
        for (int n = 0; n < 8; n++) { g0[n] = h0[id[n]]; g1[n] = h1[id[n]]; }

        float z0[9], z1[9];
#pragma unroll
        for (int k = 0; k < 9; k++) {
            float s0 = 0.0f, s1 = 0.0f;
#pragma unroll
            for (int n = 0; n < 8; n++) {
                s0 = fmaf(g0[n], v[k][n], s0);
                s1 = fmaf(g1[n], v[k][n], s1);
            }
            z0[k] = s0; z1[k] = s1;
        }

        uint4* ob = (uint4*)(nhwc +
            (((size_t)b * Hp + (py + 2)) * Wp + (px + 2)) * 64);
        for (int o8 = 0; o8 < 8; o8++) {
            __half hv[8];
#pragma unroll
            for (int q = 0; q < 8; q++) {
                int o = o8 * 8 + q;
                const float* wo = &w_s[o * 18];
                float a = b_s[o];
#pragma unroll
                for (int k = 0; k < 9; k++)
                    a = fmaf(z0[k], wo[k], fmaf(z1[k], wo[9 + k], a));
                hv[q] = __float2half_rn(fmaxf(a, 0.0f));
            }
            ob[o8] = *(uint4*)hv;
        }
    }
}

// ---------------------------------------------------------------------------
// weight transform: (32oc,64ic,5,5) fp32 -> fp16 [tap][ic][oc]
// ---------------------------------------------------------------------------
__global__ void wtransform_kernel(const float* __restrict__ w,
                                  __half* __restrict__ wh)
{
    int i = blockIdx.x * 256 + threadIdx.x;
    if (i >= 25 * 64 * 32) return;
    int tap = i / 2048;
    int r = i % 2048;
    int ic = r >> 5;
    int oc = r & 31;
    wh[i] = __float2half_rn(w[((size_t)oc * 64 + ic) * 25 + tap]);
}

// ---------------------------------------------------------------------------
// conv2 via warp-level fp16 mma (exact R6 version, proven ~500us)
// ---------------------------------------------------------------------------
__global__ __launch_bounds__(256)
void conv2_mma(const __half* __restrict__ nhwc, const __half* __restrict__ wh,
               const float* __restrict__ bias, float* __restrict__ out,
               int H, int W)
{
    __shared__ __align__(16) char As[132 * 128];    // 16,896 B
    __shared__ __align__(16) char Bs[5 * 64 * 80];  // 25,600 B

    const int Hp = H + 4, Wp = W + 4;
    int b = blockIdx.z, y = blockIdx.y;
    int x0 = blockIdx.x * 128;
    if (x0 > W - 128) x0 = W - 128;
    int tid = threadIdx.x;
    int warp = tid >> 5, lane = tid & 31;

    uint32_t As_b = smem_u32(As);
    uint32_t Bs_b = smem_u32(Bs);

    float acc[4][4];
#pragma unroll
    for (int j = 0; j < 4; j++)
#pragma unroll
        for (int q = 0; q < 4; q++) acc[j][q] = 0.0f;

    for (int dy = 0; dy < 5; dy++) {
        __syncthreads();
        const uint4* srcA = (const uint4*)(nhwc +
            ((size_t)(b * Hp + y + dy) * Wp + x0) * 64);
#pragma unroll
        for (int i = tid; i < 1056; i += 256) {
            int p = i >> 3, g = i & 7;
            *(uint4*)(As + p * 128 + ((g ^ (p & 7)) << 4)) = srcA[i];
        }
        const uint4* srcB = (const uint4*)(wh + (size_t)dy * 5 * 2048);
#pragma unroll
        for (int i = tid; i < 1280; i += 256) {
            int tap5 = i >> 8, k = (i >> 2) & 63, g = i & 3;
            *(uint4*)(Bs + tap5 * 5120 + k * 80 + g * 16) = srcB[i];
        }
        __syncthreads();

#pragma unroll
        for (int dx = 0; dx < 5; dx++) {
#pragma unroll
            for (int ks = 0; ks < 4; ks++) {
                uint32_t a0, a1, a2, a3;
                {
                    int r = warp * 16 + dx + (lane & 15);
                    int g = ks * 2 + (lane >> 4);
                    uint32_t addr = As_b + r * 128 + ((g ^ (r & 7)) << 4);
                    asm volatile(
                        "ldmatrix.sync.aligned.m8n8.x4.shared.b16 {%0,%1,%2,%3}, [%4];"
                        : "=r"(a0), "=r"(a1), "=r"(a2), "=r"(a3) : "r"(addr));
                }
#pragma unroll
                for (int j2 = 0; j2 < 2; j2++) {
                    uint32_t b0, b1, b2, b3;
                    {
                        int k = ks * 16 + (lane & 15);
                        int g = j2 * 2 + (lane >> 4);
                        uint32_t addr = Bs_b + dx * 5120 + k * 80 + g * 16;
                        asm volatile(
                            "ldmatrix.sync.aligned.m8n8.x4.trans.shared.b16 {%0,%1,%2,%3}, [%4];"
                            : "=r"(b0), "=r"(b1), "=r"(b2), "=r"(b3) : "r"(addr));
                    }
                    float* d0 = acc[j2 * 2 + 0];
                    asm volatile(
                        "mma.sync.aligned.m16n8k16.row.col.f32.f16.f16.f32 "
                        "{%0,%1,%2,%3}, {%4,%5,%6,%7}, {%8,%9}, {%0,%1,%2,%3};"
                        : "+f"(d0[0]), "+f"(d0[1]), "+f"(d0[2]), "+f"(d0[3])
                        : "r"(a0), "r"(a1), "r"(a2), "r"(a3), "r"(b0), "r"(b1));
                    float* d1 = acc[j2 * 2 + 1];
                    asm volatile(
                        "mma.sync.aligned.m16n8k16.row.col.f32.f16.f16.f32 "
                        "{%0,%1,%2,%3}, {%4,%5,%6,%7}, {%8,%9}, {%0,%1,%2,%3};"
                        : "+f"(d1[0]), "+f"(d1[1]), "+f"(d1[2]), "+f"(d1[3])
                        : "r"(a0), "r"(a1), "r"(a2), "r"(a3), "r"(b2), "r"(b3));
                }
            }
        }
    }

    int r0 = lane >> 2, c0 = (lane & 3) * 2;
    int xbase = x0 + warp * 16;
#pragma unroll
    for (int j = 0; j < 4; j++) {
        int oc0 = j * 8 + c0;
        float bs0 = __ldg(&bias[oc0]), bs1 = __ldg(&bias[oc0 + 1]);
        size_t p0 = (((size_t)b * 32 + oc0)     * H + y) * W;
        size_t p1 = (((size_t)b * 32 + oc0 + 1) * H + y) * W;
        out[p0 + xbase + r0]     = fmaxf(acc[j][0] + bs0, 0.0f);
        out[p1 + xbase + r0]     = fmaxf(acc[j][1] + bs1, 0.0f);
        out[p0 + xbase + r0 + 8] = fmaxf(acc[j][2] + bs0, 0.0f);
        out[p1 + xbase + r0 + 8] = fmaxf(acc[j][3] + bs1, 0.0f);
    }
}

// ---------------------------------------------------------------------------
// conv3: 5x5, IC=32 -> OC=1. 128x8 px tile, 4 px/thread, register segments.
// (the single change this round)
// ---------------------------------------------------------------------------
__global__ __launch_bounds__(256)
void conv3_kernel(const float* __restrict__ in, const float* __restrict__ w,
                  const float* __restrict__ bias, float* __restrict__ out,
                  int H, int W)
{
    const int ICC = 4, IC = 32;
    __shared__ __align__(16) float in_s[ICC][12][132];
    __shared__ float w_s[IC][25];

    int b  = blockIdx.z;
    int x0 = blockIdx.x * 128;
    int y0 = blockIdx.y * 8;
    int tid = threadIdx.x;
    int sx = tid & 31, sy = tid >> 5;

    for (int t = tid; t < IC * 25; t += 256) w_s[t / 25][t % 25] = w[t];

    float acc[4] = {0.f, 0.f, 0.f, 0.f};
    for (int cc = 0; cc < IC; cc += ICC) {
        __syncthreads();
        for (int t = tid; t < ICC * 12 * 132; t += 256) {
            int ic  = t / (12 * 132);
            int rem = t - ic * (12 * 132);
            int r = rem / 132, c = rem - r * 132;
            int gy = y0 - 2 + r, gx = x0 - 2 + c;
            float v = 0.f;
            if (gy >= 0 && gy < H && gx >= 0 && gx < W)
                v = in[((size_t)(b * IC + cc + ic) * H + gy) * W + gx];
            in_s[ic][r][c] = v;
        }
        __syncthreads();
#pragma unroll
        for (int ic = 0; ic < ICC; ic++) {
#pragma unroll
            for (int dy = 0; dy < 5; dy++) {
                const float* row = &in_s[ic][sy + dy][sx * 4];
                float4 Av = *(const float4*)row;
                float4 Bv = *(const float4*)(row + 4);
                float c8 = row[8];
                float v[9] = {Av.x, Av.y, Av.z, Av.w, Bv.x, Bv.y, Bv.z, Bv.w, c8};
                const float* wr = &w_s[cc + ic][dy * 5];
#pragma unroll
                for (int dx = 0; dx < 5; dx++) {
                    float wv = wr[dx];
#pragma unroll
                    for (int q = 0; q < 4; q++)
                        acc[q] = fmaf(v[dx + q], wv, acc[q]);
                }
            }
        }
    }

    int yy = y0 + sy;
    if (yy < H) {
#pragma unroll
        for (int q = 0; q < 4; q++) {
            int xx = x0 + sx * 4 + q;
            if (xx < W)
                out[((size_t)b * H + yy) * W + xx] = acc[q] + bias[0];
        }
    }
}

// ---------------------------------------------------------------------------
// Orchestration
// ---------------------------------------------------------------------------
extern "C" void kernel_launch(void* const* d_in, const int* in_sizes, int n_in,
                              void* d_out, int out_size)
{
    const float* x        = (const float*)d_in[0];
    const float* elev0    = (const float*)d_in[1];
    const float* elev1    = (const float*)d_in[2];
    const int*   psi_idx1 = (const int*)  d_in[3];
    const float* psi_val1 = (const float*)d_in[4];
    const float* w1       = (const float*)d_in[5];
    const float* b1       = (const float*)d_in[6];
    const float* cw2_1    = (const float*)d_in[7];
    const float* cb2_1    = (const float*)d_in[8];
    const float* cw3_1    = (const float*)d_in[9];
    const float* cb3_1    = (const float*)d_in[10];
    const int*   psi_idx2 = (const int*)  d_in[11];
    const float* psi_val2 = (const float*)d_in[12];
    const float* w2       = (const float*)d_in[13];
    const float* b2       = (const float*)d_in[14];
    const float* cw2_2    = (const float*)d_in[15];
    const float* cb2_2    = (const float*)d_in[16];
    const float* cw3_2    = (const float*)d_in[17];
    const float* cb3_2    = (const float*)d_in[18];
    float* out = (float*)d_out;

    float* scratch = nullptr;
    cudaGetSymbolAddress((void**)&scratch, g_scratch);
    __half* nhwcH = (__half*)(scratch + OFF_NHWCH);
    float*  bufB2 = scratch + OFF_B2;
    float*  bufH  = scratch + OFF_H;
    float*  bufY1 = scratch + OFF_Y1;
    __half* bufWH = (__half*)(scratch + OFF_WH);

    // ---------------- stage 1: 90x180 -> 180x360 ----------------
    {
        const int H = 180, W = 360, P = H * W, Hp = H + 4, Wp = W + 4;
        int total = B_ * H * W;
        upsample_concat_kernel<<<(total + 255) / 256, 256>>>(x, elev0, bufH, 90, 180);
        pad_zero_h_kernel<<<(B_ * Hp * Wp + 255) / 256, 256>>>(nhwcH, Hp, Wp);
        disco_kernel<<<(P + 255) / 256, 256>>>(bufH, psi_idx1, psi_val1, w1, b1,
                                               nhwcH, P, W, Hp, Wp);
        wtransform_kernel<<<200, 256>>>(cw2_1, bufWH);
        dim3 g2((W + 127) / 128, H, B_);
        conv2_mma<<<g2, 256>>>(nhwcH, bufWH, cb2_1, bufB2, H, W);
        dim3 g3((W + 127) / 128, (H + 7) / 8, B_);
        conv3_kernel<<<g3, 256>>>(bufB2, cw3_1, cb3_1, bufY1, H, W);
    }
    // ---------------- stage 2: 180x360 -> 360x720 ----------------
    {
        const int H = 360, W = 720, P = H * W, Hp = H + 4, Wp = W + 4;
        int total = B_ * H * W;
        upsample_concat_kernel<<<(total + 255) / 256, 256>>>(bufY1, elev1, bufH, 180, 360);
        pad_zero_h_kernel<<<(B_ * Hp * Wp + 255) / 256, 256>>>(nhwcH, Hp, Wp);
        disco_kernel<<<(P + 255) / 256, 256>>>(bufH, psi_idx2, psi_val2, w2, b2,
                                               nhwcH, P, W, Hp, Wp);
        wtransform_kernel<<<200, 256>>>(cw2_2, bufWH);
        dim3 g2((W + 127) / 128, H, B_);
        conv2_mma<<<g2, 256>>>(nhwcH, bufWH, cb2_2, bufB2, H, W);
        dim3 g3((W + 127) / 128, (H + 7) / 8, B_);
        conv3_kernel<<<g3, 256>>>(bufB2, cw3_2, cb3_2, out, H, W);
    }
}

// round 9
// speedup vs baseline: 2.2707x; 1.1244x over previous
#include <cuda_runtime.h>
#include <cuda_fp16.h>
#include <cstdint>
#include <cstddef>

// ===========================================================================
// DeepSDSphere R9: conv2 warp-M=32 (4 warps/block, halved LDSM per MMA).
// Border zeroing folded into disco (pad kernel removed) so conv2 is the 4th
// launch and lands in the ncu window.
// ===========================================================================

#define B_   4
#define F_   64

// ---------------- scratch layout (floats) -----------------------------------
#define SZ_NHWCH (4ull*364ull*724ull*64ull/2ull)   // fp16 NHWC as float count
#define SZ_B2    (4ull*32ull*360ull*720ull)
#define SZ_H     (4ull*2ull*360ull*720ull)
#define SZ_Y1    (4ull*180ull*360ull)
#define SZ_WH    (25ull*64ull*32ull/2ull)          // fp16 weights as float count
#define OFF_NHWCH 0ull
#define OFF_B2    (OFF_NHWCH + SZ_NHWCH)
#define OFF_H     (OFF_B2 + SZ_B2)
#define OFF_Y1    (OFF_H + SZ_H)
#define OFF_WH    (OFF_Y1 + SZ_Y1)
#define SCRATCH_FLOATS (OFF_WH + SZ_WH)

__device__ __align__(1024) float g_scratch[SCRATCH_FLOATS];

__device__ __forceinline__ uint32_t smem_u32(const void* p) {
    uint32_t a;
    asm("{ .reg .u64 t; cvta.to.shared.u64 t, %1; cvt.u32.u64 %0, t; }"
        : "=r"(a) : "l"(p));
    return a;
}

// ---------------------------------------------------------------------------
// bilinear 2x upsample (half-pixel) + concat -> (B,2,H2,W2) NCHW fp32
// ---------------------------------------------------------------------------
__global__ void upsample_concat_kernel(const float* __restrict__ x,
                                       const float* __restrict__ elev,
                                       float* __restrict__ out,
                                       int Hin, int Win)
{
    int H2 = Hin * 2, W2 = Win * 2;
    int total = B_ * H2 * W2;
    int idx = blockIdx.x * blockDim.x + threadIdx.x;
    if (idx >= total) return;
    int j = idx % W2;
    int t = idx / W2;
    int i = t % H2;
    int b = t / H2;

    float sy = (i + 0.5f) * 0.5f - 0.5f;
    sy = fminf(fmaxf(sy, 0.0f), (float)(Hin - 1));
    int r0 = (int)floorf(sy);
    int r1 = min(r0 + 1, Hin - 1);
    float ty = sy - (float)r0;

    float sx = (j + 0.5f) * 0.5f - 0.5f;
    sx = fminf(fmaxf(sx, 0.0f), (float)(Win - 1));
    int c0 = (int)floorf(sx);
    int c1 = min(c0 + 1, Win - 1);
    float tx = sx - (float)c0;

    const float* xb = x + (size_t)b * Hin * Win;
    float v00 = xb[r0 * Win + c0];
    float v01 = xb[r0 * Win + c1];
    float v10 = xb[r1 * Win + c0];
    float v11 = xb[r1 * Win + c1];
    float left  = v00 * (1.0f - ty) + v10 * ty;
    float right = v01 * (1.0f - ty) + v11 * ty;
    float v = left * (1.0f - tx) + right * tx;

    size_t plane = (size_t)H2 * W2;
    out[((size_t)b * 2 + 0) * plane + (size_t)i * W2 + j] = v;
    out[((size_t)b * 2 + 1) * plane + (size_t)i * W2 + j] =
        elev[(size_t)b * plane + (size_t)i * W2 + j];
}

// ---------------------------------------------------------------------------
// disco conv + bias + relu -> padded NHWC fp16, WITH border zeroing folded in.
// Blocks [0, nbMain) compute pixels; blocks >= nbMain zero the 2-wide border.
// ---------------------------------------------------------------------------
__global__ __launch_bounds__(256)
void disco_kernel(const float* __restrict__ h,
                  const int*   __restrict__ idx,
                  const float* __restrict__ val,
                  const float* __restrict__ w,
                  const float* __restrict__ bias,
                  __half* __restrict__ nhwc,
                  int P, int W, int Hp, int Wp, int nbMain)
{
    if (blockIdx.x >= nbMain) {
        // border zeroing: perB slots per batch
        int perB = 4 * Wp + (Hp - 4) * 4;
        int bi = (blockIdx.x - nbMain) * 256 + threadIdx.x;
        if (bi >= B_ * perB) return;
        int b = bi / perB;
        int r = bi % perB;
        int y, x;
        if (r < 2 * Wp)      { y = r / Wp;            x = r % Wp; }
        else if (r < 4 * Wp) { int r2 = r - 2 * Wp;   y = Hp - 2 + r2 / Wp; x = r2 % Wp; }
        else {
            int r3 = r - 4 * Wp;
            int side = r3 & 3;
            y = 2 + (r3 >> 2);
            x = (side < 2) ? side : (Wp - 4 + side);
        }
        uint4 z = make_uint4(0, 0, 0, 0);
        uint4* p = (uint4*)(nhwc + (((size_t)b * Hp + y) * Wp + x) * 64);
#pragma unroll
        for (int k = 0; k < 8; k++) p[k] = z;
        return;
    }

    __shared__ float w_s[F_ * 18];
    __shared__ float b_s[F_];
    for (int t = threadIdx.x; t < F_ * 18; t += 256) w_s[t] = w[t];
    if (threadIdx.x < F_) b_s[threadIdx.x] = bias[threadIdx.x];
    __syncthreads();

    int p = blockIdx.x * 256 + threadIdx.x;
    if (p >= P) return;
    int px = p % W, py = p / W;

    int id[8];
    const int4* ip = reinterpret_cast<const int4*>(idx + (size_t)p * 8);
    int4 ia = ip[0], ib = ip[1];
    id[0]=ia.x; id[1]=ia.y; id[2]=ia.z; id[3]=ia.w;
    id[4]=ib.x; id[5]=ib.y; id[6]=ib.z; id[7]=ib.w;

    float v[9][8];
#pragma unroll
    for (int k = 0; k < 9; k++) {
        const float4* vp = reinterpret_cast<const float4*>(val + ((size_t)k * P + p) * 8);
        float4 a = vp[0], c = vp[1];
        v[k][0]=a.x; v[k][1]=a.y; v[k][2]=a.z; v[k][3]=a.w;
        v[k][4]=c.x; v[k][5]=c.y; v[k][6]=c.z; v[k][7]=c.w;
    }

    for (int b = 0; b < B_; b++) {
        const float* h0 = h + (size_t)(b * 2 + 0) * P;
        const float* h1 = h + (size_t)(b * 2 + 1) * P;
        float g0[8], g1[8];
#pragma unroll
        for (int n = 0; n < 8; n++) { g0[n] = h0[id[n]]; g1[n] = h1[id[n]]; }

        float z0[9], z1[9];
#pragma unroll
        for (int k = 0; k < 9; k++) {
            float s0 = 0.0f, s1 = 0.0f;
#pragma unroll
            for (int n = 0; n < 8; n++) {
                s0 = fmaf(g0[n], v[k][n], s0);
                s1 = fmaf(g1[n], v[k][n], s1);
            }
            z0[k] = s0; z1[k] = s1;
        }

        uint4* ob = (uint4*)(nhwc +
            (((size_t)b * Hp + (py + 2)) * Wp + (px + 2)) * 64);
        for (int o8 = 0; o8 < 8; o8++) {
            __half hv[8];
#pragma unroll
            for (int q = 0; q < 8; q++) {
                int o = o8 * 8 + q;
                const float* wo = &w_s[o * 18];
                float a = b_s[o];
#pragma unroll
                for (int k = 0; k < 9; k++)
                    a = fmaf(z0[k], wo[k], fmaf(z1[k], wo[9 + k], a));
                hv[q] = __float2half_rn(fmaxf(a, 0.0f));
            }
            ob[o8] = *(uint4*)hv;
        }
    }
}

// ---------------------------------------------------------------------------
// weight transform: (32oc,64ic,5,5) fp32 -> fp16 [tap][ic][oc]
// ---------------------------------------------------------------------------
__global__ void wtransform_kernel(const float* __restrict__ w,
                                  __half* __restrict__ wh)
{
    int i = blockIdx.x * 256 + threadIdx.x;
    if (i >= 25 * 64 * 32) return;
    int tap = i / 2048;
    int r = i % 2048;
    int ic = r >> 5;
    int oc = r & 31;
    wh[i] = __float2half_rn(w[((size_t)oc * 64 + ic) * 25 + tap]);
}

// ---------------------------------------------------------------------------
// conv2 via warp-level fp16 mma, warp M=32: 4 warps x 32px, each B ldmatrix
// feeds 2 A-halves (LDSM:MMA = 4:8 per (dx,ks) vs 3:4 before).
// ---------------------------------------------------------------------------
__global__ __launch_bounds__(128)
void conv2_mma(const __half* __restrict__ nhwc, const __half* __restrict__ wh,
               const float* __restrict__ bias, float* __restrict__ out,
               int H, int W)
{
    __shared__ __align__(16) char As[132 * 128];    // 16,896 B
    __shared__ __align__(16) char Bs[5 * 64 * 80];  // 25,600 B

    const int Hp = H + 4, Wp = W + 4;
    int b = blockIdx.z, y = blockIdx.y;
    int x0 = blockIdx.x * 128;
    if (x0 > W - 128) x0 = W - 128;
    int tid = threadIdx.x;
    int warp = tid >> 5, lane = tid & 31;

    uint32_t As_b = smem_u32(As);
    uint32_t Bs_b = smem_u32(Bs);

    float acc[2][4][4];
#pragma unroll
    for (int m = 0; m < 2; m++)
#pragma unroll
        for (int j = 0; j < 4; j++)
#pragma unroll
            for (int q = 0; q < 4; q++) acc[m][j][q] = 0.0f;

    for (int dy = 0; dy < 5; dy++) {
        __syncthreads();
        const uint4* srcA = (const uint4*)(nhwc +
            ((size_t)(b * Hp + y + dy) * Wp + x0) * 64);
#pragma unroll
        for (int i = tid; i < 1056; i += 128) {
            int p = i >> 3, g = i & 7;
            *(uint4*)(As + p * 128 + ((g ^ (p & 7)) << 4)) = srcA[i];
        }
        const uint4* srcB = (const uint4*)(wh + (size_t)dy * 5 * 2048);
#pragma unroll
        for (int i = tid; i < 1280; i += 128) {
            int tap5 = i >> 8, k = (i >> 2) & 63, g = i & 3;
            *(uint4*)(Bs + tap5 * 5120 + k * 80 + g * 16) = srcB[i];
        }
        __syncthreads();

#pragma unroll
        for (int dx = 0; dx < 5; dx++) {
#pragma unroll
            for (int ks = 0; ks < 4; ks++) {
                // two A fragments: m-halves of the warp's 32 rows
                uint32_t a[2][4];
#pragma unroll
                for (int mh = 0; mh < 2; mh++) {
                    int r = warp * 32 + mh * 16 + dx + (lane & 15);
                    int g = ks * 2 + (lane >> 4);
                    uint32_t addr = As_b + r * 128 + ((g ^ (r & 7)) << 4);
                    asm volatile(
                        "ldmatrix.sync.aligned.m8n8.x4.shared.b16 {%0,%1,%2,%3}, [%4];"
                        : "=r"(a[mh][0]), "=r"(a[mh][1]), "=r"(a[mh][2]), "=r"(a[mh][3])
                        : "r"(addr));
                }
#pragma unroll
                for (int j2 = 0; j2 < 2; j2++) {
                    uint32_t b0, b1, b2, b3;
                    {
                        int k = ks * 16 + (lane & 15);
                        int g = j2 * 2 + (lane >> 4);
                        uint32_t addr = Bs_b + dx * 5120 + k * 80 + g * 16;
                        asm volatile(
                            "ldmatrix.sync.aligned.m8n8.x4.trans.shared.b16 {%0,%1,%2,%3}, [%4];"
                            : "=r"(b0), "=r"(b1), "=r"(b2), "=r"(b3) : "r"(addr));
                    }
#pragma unroll
                    for (int mh = 0; mh < 2; mh++) {
                        float* d0 = acc[mh][j2 * 2 + 0];
                        asm volatile(
                            "mma.sync.aligned.m16n8k16.row.col.f32.f16.f16.f32 "
                            "{%0,%1,%2,%3}, {%4,%5,%6,%7}, {%8,%9}, {%0,%1,%2,%3};"
                            : "+f"(d0[0]), "+f"(d0[1]), "+f"(d0[2]), "+f"(d0[3])
                            : "r"(a[mh][0]), "r"(a[mh][1]), "r"(a[mh][2]), "r"(a[mh][3]),
                              "r"(b0), "r"(b1));
                        float* d1 = acc[mh][j2 * 2 + 1];
                        asm volatile(
                            "mma.sync.aligned.m16n8k16.row.col.f32.f16.f16.f32 "
                            "{%0,%1,%2,%3}, {%4,%5,%6,%7}, {%8,%9}, {%0,%1,%2,%3};"
                            : "+f"(d1[0]), "+f"(d1[1]), "+f"(d1[2]), "+f"(d1[3])
                            : "r"(a[mh][0]), "r"(a[mh][1]), "r"(a[mh][2]), "r"(a[mh][3]),
                              "r"(b2), "r"(b3));
                    }
                }
            }
        }
    }

    int r0 = lane >> 2, c0 = (lane & 3) * 2;
#pragma unroll
    for (int mh = 0; mh < 2; mh++) {
        int xbase = x0 + warp * 32 + mh * 16;
#pragma unroll
        for (int j = 0; j < 4; j++) {
            int oc0 = j * 8 + c0;
            float bs0 = __ldg(&bias[oc0]), bs1 = __ldg(&bias[oc0 + 1]);
            size_t p0 = (((size_t)b * 32 + oc0)     * H + y) * W;
            size_t p1 = (((size_t)b * 32 + oc0 + 1) * H + y) * W;
            out[p0 + xbase + r0]     = fmaxf(acc[mh][j][0] + bs0, 0.0f);
            out[p1 + xbase + r0]     = fmaxf(acc[mh][j][1] + bs1, 0.0f);
            out[p0 + xbase + r0 + 8] = fmaxf(acc[mh][j][2] + bs0, 0.0f);
            out[p1 + xbase + r0 + 8] = fmaxf(acc[mh][j][3] + bs1, 0.0f);
        }
    }
}

// ---------------------------------------------------------------------------
// conv3: 5x5, IC=32 -> OC=1. 128x8 px tile, 4 px/thread (proven R8 version).
// ---------------------------------------------------------------------------
__global__ __launch_bounds__(256)
void conv3_kernel(const float* __restrict__ in, const float* __restrict__ w,
                  const float* __restrict__ bias, float* __restrict__ out,
                  int H, int W)
{
    const int ICC = 4, IC = 32;
    __shared__ __align__(16) float in_s[ICC][12][132];
    __shared__ float w_s[IC][25];

    int b  = blockIdx.z;
    int x0 = blockIdx.x * 128;
    int y0 = blockIdx.y * 8;
    int tid = threadIdx.x;
    int sx = tid & 31, sy = tid >> 5;

    for (int t = tid; t < IC * 25; t += 256) w_s[t / 25][t % 25] = w[t];

    float acc[4] = {0.f, 0.f, 0.f, 0.f};
    for (int cc = 0; cc < IC; cc += ICC) {
        __syncthreads();
        for (int t = tid; t < ICC * 12 * 132; t += 256) {
            int ic  = t / (12 * 132);
            int rem = t - ic * (12 * 132);
            int r = rem / 132, c = rem - r * 132;
            int gy = y0 - 2 + r, gx = x0 - 2 + c;
            float v = 0.f;
            if (gy >= 0 && gy < H && gx >= 0 && gx < W)
                v = in[((size_t)(b * IC + cc + ic) * H + gy) * W + gx];
            in_s[ic][r][c] = v;
        }
        __syncthreads();
#pragma unroll
        for (int ic = 0; ic < ICC; ic++) {
#pragma unroll
            for (int dy = 0; dy < 5; dy++) {
                const float* row = &in_s[ic][sy + dy][sx * 4];
                float4 Av = *(const float4*)row;
                float4 Bv = *(const float4*)(row + 4);
                float c8 = row[8];
                float v[9] = {Av.x, Av.y, Av.z, Av.w, Bv.x, Bv.y, Bv.z, Bv.w, c8};
                const float* wr = &w_s[cc + ic][dy * 5];
#pragma unroll
                for (int dx = 0; dx < 5; dx++) {
                    float wv = wr[dx];
#pragma unroll
                    for (int q = 0; q < 4; q++)
                        acc[q] = fmaf(v[dx + q], wv, acc[q]);
                }
            }
        }
    }

    int yy = y0 + sy;
    if (yy < H) {
#pragma unroll
        for (int q = 0; q < 4; q++) {
            int xx = x0 + sx * 4 + q;
            if (xx < W)
                out[((size_t)b * H + yy) * W + xx] = acc[q] + bias[0];
        }
    }
}

// ---------------------------------------------------------------------------
// Orchestration
// ---------------------------------------------------------------------------
extern "C" void kernel_launch(void* const* d_in, const int* in_sizes, int n_in,
                              void* d_out, int out_size)
{
    const float* x        = (const float*)d_in[0];
    const float* elev0    = (const float*)d_in[1];
    const float* elev1    = (const float*)d_in[2];
    const int*   psi_idx1 = (const int*)  d_in[3];
    const float* psi_val1 = (const float*)d_in[4];
    const float* w1       = (const float*)d_in[5];
    const float* b1       = (const float*)d_in[6];
    const float* cw2_1    = (const float*)d_in[7];
    const float* cb2_1    = (const float*)d_in[8];
    const float* cw3_1    = (const float*)d_in[9];
    const float* cb3_1    = (const float*)d_in[10];
    const int*   psi_idx2 = (const int*)  d_in[11];
    const float* psi_val2 = (const float*)d_in[12];
    const float* w2       = (const float*)d_in[13];
    const float* b2       = (const float*)d_in[14];
    const float* cw2_2    = (const float*)d_in[15];
    const float* cb2_2    = (const float*)d_in[16];
    const float* cw3_2    = (const float*)d_in[17];
    const float* cb3_2    = (const float*)d_in[18];
    float* out = (float*)d_out;

    float* scratch = nullptr;
    cudaGetSymbolAddress((void**)&scratch, g_scratch);
    __half* nhwcH = (__half*)(scratch + OFF_NHWCH);
    float*  bufB2 = scratch + OFF_B2;
    float*  bufH  = scratch + OFF_H;
    float*  bufY1 = scratch + OFF_Y1;
    __half* bufWH = (__half*)(scratch + OFF_WH);

    // ---------------- stage 1: 90x180 -> 180x360 ----------------
    {
        const int H = 180, W = 360, P = H * W, Hp = H + 4, Wp = W + 4;
        int total = B_ * H * W;
        int nbMain = (P + 255) / 256;
        int perB = 4 * Wp + (Hp - 4) * 4;
        int nbBorder = (B_ * perB + 255) / 256;
        upsample_concat_kernel<<<(total + 255) / 256, 256>>>(x, elev0, bufH, 90, 180);
        disco_kernel<<<nbMain + nbBorder, 256>>>(bufH, psi_idx1, psi_val1, w1, b1,
                                                 nhwcH, P, W, Hp, Wp, nbMain);
        wtransform_kernel<<<200, 256>>>(cw2_1, bufWH);
        dim3 g2((W + 127) / 128, H, B_);
        conv2_mma<<<g2, 128>>>(nhwcH, bufWH, cb2_1, bufB2, H, W);   // 4th launch
        dim3 g3((W + 127) / 128, (H + 7) / 8, B_);
        conv3_kernel<<<g3, 256>>>(bufB2, cw3_1, cb3_1, bufY1, H, W);
    }
    // ---------------- stage 2: 180x360 -> 360x720 ----------------
    {
        const int H = 360, W = 720, P = H * W, Hp = H + 4, Wp = W + 4;
        int total = B_ * H * W;
        int nbMain = (P + 255) / 256;
        int perB = 4 * Wp + (Hp - 4) * 4;
        int nbBorder = (B_ * perB + 255) / 256;
        upsample_concat_kernel<<<(total + 255) / 256, 256>>>(bufY1, elev1, bufH, 180, 360);
        disco_kernel<<<nbMain + nbBorder, 256>>>(bufH, psi_idx2, psi_val2, w2, b2,
                                                 nhwcH, P, W, Hp, Wp, nbMain);
        wtransform_kernel<<<200, 256>>>(cw2_2, bufWH);
        dim3 g2((W + 127) / 128, H, B_);
        conv2_mma<<<g2, 128>>>(nhwcH, bufWH, cb2_2, bufB2, H, W);
        dim3 g3((W + 127) / 128, (H + 7) / 8, B_);
        conv3_kernel<<<g3, 256>>>(bufB2, cw3_2, cb3_2, out, H, W);
    }
}

// round 10
// speedup vs baseline: 2.3164x; 1.0202x over previous
#include <cuda_runtime.h>
#include <cuda_fp16.h>
#include <cstdint>
#include <cstddef>

// ===========================================================================
// DeepSDSphere R10: conv2 warp-M=64 (2 warps/block, 64 threads), LDSM
// wavefronts per MMA cut from 0.5 to 0.375. All else identical to R9.
// ===========================================================================

#define B_   4
#define F_   64

// ---------------- scratch layout (floats) -----------------------------------
#define SZ_NHWCH (4ull*364ull*724ull*64ull/2ull)   // fp16 NHWC as float count
#define SZ_B2    (4ull*32ull*360ull*720ull)
#define SZ_H     (4ull*2ull*360ull*720ull)
#define SZ_Y1    (4ull*180ull*360ull)
#define SZ_WH    (25ull*64ull*32ull/2ull)          // fp16 weights as float count
#define OFF_NHWCH 0ull
#define OFF_B2    (OFF_NHWCH + SZ_NHWCH)
#define OFF_H     (OFF_B2 + SZ_B2)
#define OFF_Y1    (OFF_H + SZ_H)
#define OFF_WH    (OFF_Y1 + SZ_Y1)
#define SCRATCH_FLOATS (OFF_WH + SZ_WH)

__device__ __align__(1024) float g_scratch[SCRATCH_FLOATS];

__device__ __forceinline__ uint32_t smem_u32(const void* p) {
    uint32_t a;
    asm("{ .reg .u64 t; cvta.to.shared.u64 t, %1; cvt.u32.u64 %0, t; }"
        : "=r"(a) : "l"(p));
    return a;
}

// ---------------------------------------------------------------------------
// bilinear 2x upsample (half-pixel) + concat -> (B,2,H2,W2) NCHW fp32
// ---------------------------------------------------------------------------
__global__ void upsample_concat_kernel(const float* __restrict__ x,
                                       const float* __restrict__ elev,
                                       float* __restrict__ out,
                                       int Hin, int Win)
{
    int H2 = Hin * 2, W2 = Win * 2;
    int total = B_ * H2 * W2;
    int idx = blockIdx.x * blockDim.x + threadIdx.x;
    if (idx >= total) return;
    int j = idx % W2;
    int t = idx / W2;
    int i = t % H2;
    int b = t / H2;

    float sy = (i + 0.5f) * 0.5f - 0.5f;
    sy = fminf(fmaxf(sy, 0.0f), (float)(Hin - 1));
    int r0 = (int)floorf(sy);
    int r1 = min(r0 + 1, Hin - 1);
    float ty = sy - (float)r0;

    float sx = (j + 0.5f) * 0.5f - 0.5f;
    sx = fminf(fmaxf(sx, 0.0f), (float)(Win - 1));
    int c0 = (int)floorf(sx);
    int c1 = min(c0 + 1, Win - 1);
    float tx = sx - (float)c0;

    const float* xb = x + (size_t)b * Hin * Win;
    float v00 = xb[r0 * Win + c0];
    float v01 = xb[r0 * Win + c1];
    float v10 = xb[r1 * Win + c0];
    float v11 = xb[r1 * Win + c1];
    float left  = v00 * (1.0f - ty) + v10 * ty;
    float right = v01 * (1.0f - ty) + v11 * ty;
    float v = left * (1.0f - tx) + right * tx;

    size_t plane = (size_t)H2 * W2;
    out[((size_t)b * 2 + 0) * plane + (size_t)i * W2 + j] = v;
    out[((size_t)b * 2 + 1) * plane + (size_t)i * W2 + j] =
        elev[(size_t)b * plane + (size_t)i * W2 + j];
}

// ---------------------------------------------------------------------------
// disco conv + bias + relu -> padded NHWC fp16, border zeroing folded in.
// ---------------------------------------------------------------------------
__global__ __launch_bounds__(256)
void disco_kernel(const float* __restrict__ h,
                  const int*   __restrict__ idx,
                  const float* __restrict__ val,
                  const float* __restrict__ w,
                  const float* __restrict__ bias,
                  __half* __restrict__ nhwc,
                  int P, int W, int Hp, int Wp, int nbMain)
{
    if (blockIdx.x >= nbMain) {
        int perB = 4 * Wp + (Hp - 4) * 4;
        int bi = (blockIdx.x - nbMain) * 256 + threadIdx.x;
        if (bi >= B_ * perB) return;
        int b = bi / perB;
        int r = bi % perB;
        int y, x;
        if (r < 2 * Wp)      { y = r / Wp;            x = r % Wp; }
        else if (r < 4 * Wp) { int r2 = r - 2 * Wp;   y = Hp - 2 + r2 / Wp; x = r2 % Wp; }
        else {
            int r3 = r - 4 * Wp;
            int side = r3 & 3;
            y = 2 + (r3 >> 2);
            x = (side < 2) ? side : (Wp - 4 + side);
        }
        uint4 z = make_uint4(0, 0, 0, 0);
        uint4* p = (uint4*)(nhwc + (((size_t)b * Hp + y) * Wp + x) * 64);
#pragma unroll
        for (int k = 0; k < 8; k++) p[k] = z;
        return;
    }

    __shared__ float w_s[F_ * 18];
    __shared__ float b_s[F_];
    for (int t = threadIdx.x; t < F_ * 18; t += 256) w_s[t] = w[t];
    if (threadIdx.x < F_) b_s[threadIdx.x] = bias[threadIdx.x];
    __syncthreads();

    int p = blockIdx.x * 256 + threadIdx.x;
    if (p >= P) return;
    int px = p % W, py = p / W;

    int id[8];
    const int4* ip = reinterpret_cast<const int4*>(idx + (size_t)p * 8);
    int4 ia = ip[0], ib = ip[1];
    id[0]=ia.x; id[1]=ia.y; id[2]=ia.z; id[3]=ia.w;
    id[4]=ib.x; id[5]=ib.y; id[6]=ib.z; id[7]=ib.w;

    float v[9][8];
#pragma unroll
    for (int k = 0; k < 9; k++) {
        const float4* vp = reinterpret_cast<const float4*>(val + ((size_t)k * P + p) * 8);
        float4 a = vp[0], c = vp[1];
        v[k][0]=a.x; v[k][1]=a.y; v[k][2]=a.z; v[k][3]=a.w;
        v[k][4]=c.x; v[k][5]=c.y; v[k][6]=c.z; v[k][7]=c.w;
    }

    for (int b = 0; b < B_; b++) {
        const float* h0 = h + (size_t)(b * 2 + 0) * P;
        const float* h1 = h + (size_t)(b * 2 + 1) * P;
        float g0[8], g1[8];
#pragma unroll
        for (int n = 0; n < 8; n++) { g0[n] = h0[id[n]]; g1[n] = h1[id[n]]; }

        float z0[9], z1[9];
#pragma unroll
        for (int k = 0; k < 9; k++) {
            float s0 = 0.0f, s1 = 0.0f;
#pragma unroll
            for (int n = 0; n < 8; n++) {
                s0 = fmaf(g0[n], v[k][n], s0);
                s1 = fmaf(g1[n], v[k][n], s1);
            }
            z0[k] = s0; z1[k] = s1;
        }

        uint4* ob = (uint4*)(nhwc +
            (((size_t)b * Hp + (py + 2)) * Wp + (px + 2)) * 64);
        for (int o8 = 0; o8 < 8; o8++) {
            __half hv[8];
#pragma unroll
            for (int q = 0; q < 8; q++) {
                int o = o8 * 8 + q;
                const float* wo = &w_s[o * 18];
                float a = b_s[o];
#pragma unroll
                for (int k = 0; k < 9; k++)
                    a = fmaf(z0[k], wo[k], fmaf(z1[k], wo[9 + k], a));
                hv[q] = __float2half_rn(fmaxf(a, 0.0f));
            }
            ob[o8] = *(uint4*)hv;
        }
    }
}

// ---------------------------------------------------------------------------
// weight transform: (32oc,64ic,5,5) fp32 -> fp16 [tap][ic][oc]
// ---------------------------------------------------------------------------
__global__ void wtransform_kernel(const float* __restrict__ w,
                                  __half* __restrict__ wh)
{
    int i = blockIdx.x * 256 + threadIdx.x;
    if (i >= 25 * 64 * 32) return;
    int tap = i / 2048;
    int r = i % 2048;
    int ic = r >> 5;
    int oc = r & 31;
    wh[i] = __float2half_rn(w[((size_t)oc * 64 + ic) * 25 + tap]);
}

// ---------------------------------------------------------------------------
// conv2 via warp-level fp16 mma, warp M=64: 2 warps x 64px per block.
// Per (dx,ks): 4 A-LDSM + 2 B-LDSM -> 16 MMA (ratio 0.375).
// ---------------------------------------------------------------------------
__global__ __launch_bounds__(64)
void conv2_mma(const __half* __restrict__ nhwc, const __half* __restrict__ wh,
               const float* __restrict__ bias, float* __restrict__ out,
               int H, int W)
{
    __shared__ __align__(16) char As[132 * 128];    // 16,896 B
    __shared__ __align__(16) char Bs[5 * 64 * 80];  // 25,600 B

    const int Hp = H + 4, Wp = W + 4;
    int b = blockIdx.z, y = blockIdx.y;
    int x0 = blockIdx.x * 128;
    if (x0 > W - 128) x0 = W - 128;
    int tid = threadIdx.x;
    int warp = tid >> 5, lane = tid & 31;

    uint32_t As_b = smem_u32(As);
    uint32_t Bs_b = smem_u32(Bs);

    float acc[4][4][4];   // [mh 0..3][n-chunk][reg]
#pragma unroll
    for (int m = 0; m < 4; m++)
#pragma unroll
        for (int j = 0; j < 4; j++)
#pragma unroll
            for (int q = 0; q < 4; q++) acc[m][j][q] = 0.0f;

    for (int dy = 0; dy < 5; dy++) {
        __syncthreads();
        const uint4* srcA = (const uint4*)(nhwc +
            ((size_t)(b * Hp + y + dy) * Wp + x0) * 64);
        for (int i = tid; i < 1056; i += 64) {
            int p = i >> 3, g = i & 7;
            *(uint4*)(As + p * 128 + ((g ^ (p & 7)) << 4)) = srcA[i];
        }
        const uint4* srcB = (const uint4*)(wh + (size_t)dy * 5 * 2048);
        for (int i = tid; i < 1280; i += 64) {
            int tap5 = i >> 8, k = (i >> 2) & 63, g = i & 3;
            *(uint4*)(Bs + tap5 * 5120 + k * 80 + g * 16) = srcB[i];
        }
        __syncthreads();

#pragma unroll
        for (int dx = 0; dx < 5; dx++) {
#pragma unroll
            for (int ks = 0; ks < 4; ks++) {
                // four A fragments: m-quarters of the warp's 64 rows
                uint32_t a[4][4];
#pragma unroll
                for (int mh = 0; mh < 4; mh++) {
                    int r = warp * 64 + mh * 16 + dx + (lane & 15);
                    int g = ks * 2 + (lane >> 4);
                    uint32_t addr = As_b + r * 128 + ((g ^ (r & 7)) << 4);
                    asm volatile(
                        "ldmatrix.sync.aligned.m8n8.x4.shared.b16 {%0,%1,%2,%3}, [%4];"
                        : "=r"(a[mh][0]), "=r"(a[mh][1]), "=r"(a[mh][2]), "=r"(a[mh][3])
                        : "r"(addr));
                }
#pragma unroll
                for (int j2 = 0; j2 < 2; j2++) {
                    uint32_t b0, b1, b2, b3;
                    {
                        int k = ks * 16 + (lane & 15);
                        int g = j2 * 2 + (lane >> 4);
                        uint32_t addr = Bs_b + dx * 5120 + k * 80 + g * 16;
                        asm volatile(
                            "ldmatrix.sync.aligned.m8n8.x4.trans.shared.b16 {%0,%1,%2,%3}, [%4];"
                            : "=r"(b0), "=r"(b1), "=r"(b2), "=r"(b3) : "r"(addr));
                    }
#pragma unroll
                    for (int mh = 0; mh < 4; mh++) {
                        float* d0 = acc[mh][j2 * 2 + 0];
                        asm volatile(
                            "mma.sync.aligned.m16n8k16.row.col.f32.f16.f16.f32 "
                            "{%0,%1,%2,%3}, {%4,%5,%6,%7}, {%8,%9}, {%0,%1,%2,%3};"
                            : "+f"(d0[0]), "+f"(d0[1]), "+f"(d0[2]), "+f"(d0[3])
                            : "r"(a[mh][0]), "r"(a[mh][1]), "r"(a[mh][2]), "r"(a[mh][3]),
                              "r"(b0), "r"(b1));
                        float* d1 = acc[mh][j2 * 2 + 1];
                        asm volatile(
                            "mma.sync.aligned.m16n8k16.row.col.f32.f16.f16.f32 "
                            "{%0,%1,%2,%3}, {%4,%5,%6,%7}, {%8,%9}, {%0,%1,%2,%3};"
                            : "+f"(d1[0]), "+f"(d1[1]), "+f"(d1[2]), "+f"(d1[3])
                            : "r"(a[mh][0]), "r"(a[mh][1]), "r"(a[mh][2]), "r"(a[mh][3]),
                              "r"(b2), "r"(b3));
                    }
                }
            }
        }
    }

    int r0 = lane >> 2, c0 = (lane & 3) * 2;
#pragma unroll
    for (int mh = 0; mh < 4; mh++) {
        int xbase = x0 + warp * 64 + mh * 16;
#pragma unroll
        for (int j = 0; j < 4; j++) {
            int oc0 = j * 8 + c0;
            float bs0 = __ldg(&bias[oc0]), bs1 = __ldg(&bias[oc0 + 1]);
            size_t p0 = (((size_t)b * 32 + oc0)     * H + y) * W;
            size_t p1 = (((size_t)b * 32 + oc0 + 1) * H + y) * W;
            out[p0 + xbase + r0]     = fmaxf(acc[mh][j][0] + bs0, 0.0f);
            out[p1 + xbase + r0]     = fmaxf(acc[mh][j][1] + bs1, 0.0f);
            out[p0 + xbase + r0 + 8] = fmaxf(acc[mh][j][2] + bs0, 0.0f);
            out[p1 + xbase + r0 + 8] = fmaxf(acc[mh][j][3] + bs1, 0.0f);
        }
    }
}

// ---------------------------------------------------------------------------
// conv3: 5x5, IC=32 -> OC=1. 128x8 px tile, 4 px/thread (proven R8 version).
// ---------------------------------------------------------------------------
__global__ __launch_bounds__(256)
void conv3_kernel(const float* __restrict__ in, const float* __restrict__ w,
                  const float* __restrict__ bias, float* __restrict__ out,
                  int H, int W)
{
    const int ICC = 4, IC = 32;
    __shared__ __align__(16) float in_s[ICC][12][132];
    __shared__ float w_s[IC][25];

    int b  = blockIdx.z;
    int x0 = blockIdx.x * 128;
    int y0 = blockIdx.y * 8;
    int tid = threadIdx.x;
    int sx = tid & 31, sy = tid >> 5;

    for (int t = tid; t < IC * 25; t += 256) w_s[t / 25][t % 25] = w[t];

    float acc[4] = {0.f, 0.f, 0.f, 0.f};
    for (int cc = 0; cc < IC; cc += ICC) {
        __syncthreads();
        for (int t = tid; t < ICC * 12 * 132; t += 256) {
            int ic  = t / (12 * 132);
            int rem = t - ic * (12 * 132);
            int r = rem / 132, c = rem - r * 132;
            int gy = y0 - 2 + r, gx = x0 - 2 + c;
            float v = 0.f;
            if (gy >= 0 && gy < H && gx >= 0 && gx < W)
                v = in[((size_t)(b * IC + cc + ic) * H + gy) * W + gx];
            in_s[ic][r][c] = v;
        }
        __syncthreads();
#pragma unroll
        for (int ic = 0; ic < ICC; ic++) {
#pragma unroll
            for (int dy = 0; dy < 5; dy++) {
                const float* row = &in_s[ic][sy + dy][sx * 4];
                float4 Av = *(const float4*)row;
                float4 Bv = *(const float4*)(row + 4);
                float c8 = row[8];
                float v[9] = {Av.x, Av.y, Av.z, Av.w, Bv.x, Bv.y, Bv.z, Bv.w, c8};
                const float* wr = &w_s[cc + ic][dy * 5];
#pragma unroll
                for (int dx = 0; dx < 5; dx++) {
                    float wv = wr[dx];
#pragma unroll
                    for (int q = 0; q < 4; q++)
                        acc[q] = fmaf(v[dx + q], wv, acc[q]);
                }
            }
        }
    }

    int yy = y0 + sy;
    if (yy < H) {
#pragma unroll
        for (int q = 0; q < 4; q++) {
            int xx = x0 + sx * 4 + q;
            if (xx < W)
                out[((size_t)b * H + yy) * W + xx] = acc[q] + bias[0];
        }
    }
}

// ---------------------------------------------------------------------------
// Orchestration
// ---------------------------------------------------------------------------
extern "C" void kernel_launch(void* const* d_in, const int* in_sizes, int n_in,
                              void* d_out, int out_size)
{
    const float* x        = (const float*)d_in[0];
    const float* elev0    = (const float*)d_in[1];
    const float* elev1    = (const float*)d_in[2];
    const int*   psi_idx1 = (const int*)  d_in[3];
    const float* psi_val1 = (const float*)d_in[4];
    const float* w1       = (const float*)d_in[5];
    const float* b1       = (const float*)d_in[6];
    const float* cw2_1    = (const float*)d_in[7];
    const float* cb2_1    = (const float*)d_in[8];
    const float* cw3_1    = (const float*)d_in[9];
    const float* cb3_1    = (const float*)d_in[10];
    const int*   psi_idx2 = (const int*)  d_in[11];
    const float* psi_val2 = (const float*)d_in[12];
    const float* w2       = (const float*)d_in[13];
    const float* b2       = (const float*)d_in[14];
    const float* cw2_2    = (const float*)d_in[15];
    const float* cb2_2    = (const float*)d_in[16];
    const float* cw3_2    = (const float*)d_in[17];
    const float* cb3_2    = (const float*)d_in[18];
    float* out = (float*)d_out;

    float* scratch = nullptr;
    cudaGetSymbolAddress((void**)&scratch, g_scratch);
    __half* nhwcH = (__half*)(scratch + OFF_NHWCH);
    float*  bufB2 = scratch + OFF_B2;
    float*  bufH  = scratch + OFF_H;
    float*  bufY1 = scratch + OFF_Y1;
    __half* bufWH = (__half*)(scratch + OFF_WH);

    // ---------------- stage 1: 90x180 -> 180x360 ----------------
    {
        const int H = 180, W = 360, P = H * W, Hp = H + 4, Wp = W + 4;
        int total = B_ * H * W;
        int nbMain = (P + 255) / 256;
        int perB = 4 * Wp + (Hp - 4) * 4;
        int nbBorder = (B_ * perB + 255) / 256;
        upsample_concat_kernel<<<(total + 255) / 256, 256>>>(x, elev0, bufH, 90, 180);
        disco_kernel<<<nbMain + nbBorder, 256>>>(bufH, psi_idx1, psi_val1, w1, b1,
                                                 nhwcH, P, W, Hp, Wp, nbMain);
        wtransform_kernel<<<200, 256>>>(cw2_1, bufWH);
        dim3 g2((W + 127) / 128, H, B_);
        conv2_mma<<<g2, 64>>>(nhwcH, bufWH, cb2_1, bufB2, H, W);   // 4th launch
        dim3 g3((W + 127) / 128, (H + 7) / 8, B_);
        conv3_kernel<<<g3, 256>>>(bufB2, cw3_1, cb3_1, bufY1, H, W);
    }
    // ---------------- stage 2: 180x360 -> 360x720 ----------------
    {
        const int H = 360, W = 720, P = H * W, Hp = H + 4, Wp = W + 4;
        int total = B_ * H * W;
        int nbMain = (P + 255) / 256;
        int perB = 4 * Wp + (Hp - 4) * 4;
        int nbBorder = (B_ * perB + 255) / 256;
        upsample_concat_kernel<<<(total + 255) / 256, 256>>>(bufY1, elev1, bufH, 180, 360);
        disco_kernel<<<nbMain + nbBorder, 256>>>(bufH, psi_idx2, psi_val2, w2, b2,
                                                 nhwcH, P, W, Hp, Wp, nbMain);
        wtransform_kernel<<<200, 256>>>(cw2_2, bufWH);
        dim3 g2((W + 127) / 128, H, B_);
        conv2_mma<<<g2, 64>>>(nhwcH, bufWH, cb2_2, bufB2, H, W);
        dim3 g3((W + 127) / 128, (H + 7) / 8, B_);
        conv3_kernel<<<g3, 256>>>(bufB2, cw3_2, cb3_2, out, H, W);
    }
}

// round 11
// speedup vs baseline: 2.4360x; 1.0516x over previous
#include <cuda_runtime.h>
#include <cuda_fp16.h>
#include <cstdint>
#include <cstddef>

// ===========================================================================
// DeepSDSphere R11: conv2 templated on warps/block. Stage2 uses NW=4
// (TW=256px, dynamic smem 58.9KB, 3 blocks/SM) halving B-staging per pixel;
// stage1 keeps NW=2. Inner loop identical to proven R10 M=64 kernel.
// ===========================================================================

#define B_   4
#define F_   64

// ---------------- scratch layout (floats) -----------------------------------
#define SZ_NHWCH (4ull*364ull*724ull*64ull/2ull)   // fp16 NHWC as float count
#define SZ_B2    (4ull*32ull*360ull*720ull)
#define SZ_H     (4ull*2ull*360ull*720ull)
#define SZ_Y1    (4ull*180ull*360ull)
#define SZ_WH    (25ull*64ull*32ull/2ull)          // fp16 weights as float count
#define OFF_NHWCH 0ull
#define OFF_B2    (OFF_NHWCH + SZ_NHWCH)
#define OFF_H     (OFF_B2 + SZ_B2)
#define OFF_Y1    (OFF_H + SZ_H)
#define OFF_WH    (OFF_Y1 + SZ_Y1)
#define SCRATCH_FLOATS (OFF_WH + SZ_WH)

__device__ __align__(1024) float g_scratch[SCRATCH_FLOATS];

__device__ __forceinline__ uint32_t smem_u32(const void* p) {
    uint32_t a;
    asm("{ .reg .u64 t; cvta.to.shared.u64 t, %1; cvt.u32.u64 %0, t; }"
        : "=r"(a) : "l"(p));
    return a;
}

// ---------------------------------------------------------------------------
// bilinear 2x upsample (half-pixel) + concat -> (B,2,H2,W2) NCHW fp32
// ---------------------------------------------------------------------------
__global__ void upsample_concat_kernel(const float* __restrict__ x,
                                       const float* __restrict__ elev,
                                       float* __restrict__ out,
                                       int Hin, int Win)
{
    int H2 = Hin * 2, W2 = Win * 2;
    int total = B_ * H2 * W2;
    int idx = blockIdx.x * blockDim.x + threadIdx.x;
    if (idx >= total) return;
    int j = idx % W2;
    int t = idx / W2;
    int i = t % H2;
    int b = t / H2;

    float sy = (i + 0.5f) * 0.5f - 0.5f;
    sy = fminf(fmaxf(sy, 0.0f), (float)(Hin - 1));
    int r0 = (int)floorf(sy);
    int r1 = min(r0 + 1, Hin - 1);
    float ty = sy - (float)r0;

    float sx = (j + 0.5f) * 0.5f - 0.5f;
    sx = fminf(fmaxf(sx, 0.0f), (float)(Win - 1));
    int c0 = (int)floorf(sx);
    int c1 = min(c0 + 1, Win - 1);
    float tx = sx - (float)c0;

    const float* xb = x + (size_t)b * Hin * Win;
    float v00 = xb[r0 * Win + c0];
    float v01 = xb[r0 * Win + c1];
    float v10 = xb[r1 * Win + c0];
    float v11 = xb[r1 * Win + c1];
    float left  = v00 * (1.0f - ty) + v10 * ty;
    float right = v01 * (1.0f - ty) + v11 * ty;
    float v = left * (1.0f - tx) + right * tx;

    size_t plane = (size_t)H2 * W2;
    out[((size_t)b * 2 + 0) * plane + (size_t)i * W2 + j] = v;
    out[((size_t)b * 2 + 1) * plane + (size_t)i * W2 + j] =
        elev[(size_t)b * plane + (size_t)i * W2 + j];
}

// ---------------------------------------------------------------------------
// disco conv + bias + relu -> padded NHWC fp16, border zeroing folded in.
// ---------------------------------------------------------------------------
__global__ __launch_bounds__(256)
void disco_kernel(const float* __restrict__ h,
                  const int*   __restrict__ idx,
                  const float* __restrict__ val,
                  const float* __restrict__ w,
                  const float* __restrict__ bias,
                  __half* __restrict__ nhwc,
                  int P, int W, int Hp, int Wp, int nbMain)
{
    if (blockIdx.x >= nbMain) {
        int perB = 4 * Wp + (Hp - 4) * 4;
        int bi = (blockIdx.x - nbMain) * 256 + threadIdx.x;
        if (bi >= B_ * perB) return;
        int b = bi / perB;
        int r = bi % perB;
        int y, x;
        if (r < 2 * Wp)      { y = r / Wp;            x = r % Wp; }
        else if (r < 4 * Wp) { int r2 = r - 2 * Wp;   y = Hp - 2 + r2 / Wp; x = r2 % Wp; }
        else {
            int r3 = r - 4 * Wp;
            int side = r3 & 3;
            y = 2 + (r3 >> 2);
            x = (side < 2) ? side : (Wp - 4 + side);
        }
        uint4 z = make_uint4(0, 0, 0, 0);
        uint4* p = (uint4*)(nhwc + (((size_t)b * Hp + y) * Wp + x) * 64);
#pragma unroll
        for (int k = 0; k < 8; k++) p[k] = z;
        return;
    }

    __shared__ float w_s[F_ * 18];
    __shared__ float b_s[F_];
    for (int t = threadIdx.x; t < F_ * 18; t += 256) w_s[t] = w[t];
    if (threadIdx.x < F_) b_s[threadIdx.x] = bias[threadIdx.x];
    __syncthreads();

    int p = blockIdx.x * 256 + threadIdx.x;
    if (p >= P) return;
    int px = p % W, py = p / W;

    int id[8];
    const int4* ip = reinterpret_cast<const int4*>(idx + (size_t)p * 8);
    int4 ia = ip[0], ib = ip[1];
    id[0]=ia.x; id[1]=ia.y; id[2]=ia.z; id[3]=ia.w;
    id[4]=ib.x; id[5]=ib.y; id[6]=ib.z; id[7]=ib.w;

    float v[9][8];
#pragma unroll
    for (int k = 0; k < 9; k++) {
        const float4* vp = reinterpret_cast<const float4*>(val + ((size_t)k * P + p) * 8);
        float4 a = vp[0], c = vp[1];
        v[k][0]=a.x; v[k][1]=a.y; v[k][2]=a.z; v[k][3]=a.w;
        v[k][4]=c.x; v[k][5]=c.y; v[k][6]=c.z; v[k][7]=c.w;
    }

    for (int b = 0; b < B_; b++) {
        const float* h0 = h + (size_t)(b * 2 + 0) * P;
        const float* h1 = h + (size_t)(b * 2 + 1) * P;
        float g0[8], g1[8];
#pragma unroll
        for (int n = 0; n < 8; n++) { g0[n] = h0[id[n]]; g1[n] = h1[id[n]]; }

        float z0[9], z1[9];
#pragma unroll
        for (int k = 0; k < 9; k++) {
            float s0 = 0.0f, s1 = 0.0f;
#pragma unroll
            for (int n = 0; n < 8; n++) {
                s0 = fmaf(g0[n], v[k][n], s0);
                s1 = fmaf(g1[n], v[k][n], s1);
            }
            z0[k] = s0; z1[k] = s1;
        }

        uint4* ob = (uint4*)(nhwc +
            (((size_t)b * Hp + (py + 2)) * Wp + (px + 2)) * 64);
        for (int o8 = 0; o8 < 8; o8++) {
            __half hv[8];
#pragma unroll
            for (int q = 0; q < 8; q++) {
                int o = o8 * 8 + q;
                const float* wo = &w_s[o * 18];
                float a = b_s[o];
#pragma unroll
                for (int k = 0; k < 9; k++)
                    a = fmaf(z0[k], wo[k], fmaf(z1[k], wo[9 + k], a));
                hv[q] = __float2half_rn(fmaxf(a, 0.0f));
            }
            ob[o8] = *(uint4*)hv;
        }
    }
}

// ---------------------------------------------------------------------------
// weight transform: (32oc,64ic,5,5) fp32 -> fp16 [tap][ic][oc]
// ---------------------------------------------------------------------------
__global__ void wtransform_kernel(const float* __restrict__ w,
                                  __half* __restrict__ wh)
{
    int i = blockIdx.x * 256 + threadIdx.x;
    if (i >= 25 * 64 * 32) return;
    int tap = i / 2048;
    int r = i % 2048;
    int ic = r >> 5;
    int oc = r & 31;
    wh[i] = __float2half_rn(w[((size_t)oc * 64 + ic) * 25 + tap]);
}

// ---------------------------------------------------------------------------
// conv2 via warp-level fp16 mma, warp M=64, NW warps/block (TW = NW*64 px).
// Dynamic smem: A (TW+4)*128 B, then B 25600 B.
// ---------------------------------------------------------------------------
template<int NW>
__global__ __launch_bounds__(NW * 32)
void conv2_mma(const __half* __restrict__ nhwc, const __half* __restrict__ wh,
               const float* __restrict__ bias, float* __restrict__ out,
               int H, int W)
{
    constexpr int TW = NW * 64;
    constexpr int A_BYTES = (TW + 4) * 128;
    extern __shared__ __align__(16) char sm[];
    char* As = sm;
    char* Bs = sm + A_BYTES;

    const int Hp = H + 4, Wp = W + 4;
    int b = blockIdx.z, y = blockIdx.y;
    int x0 = blockIdx.x * TW;
    if (x0 > W - TW) x0 = W - TW;
    int tid = threadIdx.x;
    int warp = tid >> 5, lane = tid & 31;

    uint32_t As_b = smem_u32(As);
    uint32_t Bs_b = smem_u32(Bs);

    float acc[4][4][4];   // [mh 0..3][n-chunk][reg]
#pragma unroll
    for (int m = 0; m < 4; m++)
#pragma unroll
        for (int j = 0; j < 4; j++)
#pragma unroll
            for (int q = 0; q < 4; q++) acc[m][j][q] = 0.0f;

    for (int dy = 0; dy < 5; dy++) {
        __syncthreads();
        const uint4* srcA = (const uint4*)(nhwc +
            ((size_t)(b * Hp + y + dy) * Wp + x0) * 64);
        for (int i = tid; i < (TW + 4) * 8; i += NW * 32) {
            int p = i >> 3, g = i & 7;
            *(uint4*)(As + p * 128 + ((g ^ (p & 7)) << 4)) = srcA[i];
        }
        const uint4* srcB = (const uint4*)(wh + (size_t)dy * 5 * 2048);
        for (int i = tid; i < 1280; i += NW * 32) {
            int tap5 = i >> 8, k = (i >> 2) & 63, g = i & 3;
            *(uint4*)(Bs + tap5 * 5120 + k * 80 + g * 16) = srcB[i];
        }
        __syncthreads();

#pragma unroll
        for (int dx = 0; dx < 5; dx++) {
#pragma unroll
            for (int ks = 0; ks < 4; ks++) {
                // four A fragments: m-quarters of the warp's 64 rows
                uint32_t a[4][4];
#pragma unroll
                for (int mh = 0; mh < 4; mh++) {
                    int r = warp * 64 + mh * 16 + dx + (lane & 15);
                    int g = ks * 2 + (lane >> 4);
                    uint32_t addr = As_b + r * 128 + ((g ^ (r & 7)) << 4);
                    asm volatile(
                        "ldmatrix.sync.aligned.m8n8.x4.shared.b16 {%0,%1,%2,%3}, [%4];"
                        : "=r"(a[mh][0]), "=r"(a[mh][1]), "=r"(a[mh][2]), "=r"(a[mh][3])
                        : "r"(addr));
                }
#pragma unroll
                for (int j2 = 0; j2 < 2; j2++) {
                    uint32_t b0, b1, b2, b3;
                    {
                        int k = ks * 16 + (lane & 15);
                        int g = j2 * 2 + (lane >> 4);
                        uint32_t addr = Bs_b + dx * 5120 + k * 80 + g * 16;
                        asm volatile(
                            "ldmatrix.sync.aligned.m8n8.x4.trans.shared.b16 {%0,%1,%2,%3}, [%4];"
                            : "=r"(b0), "=r"(b1), "=r"(b2), "=r"(b3) : "r"(addr));
                    }
#pragma unroll
                    for (int mh = 0; mh < 4; mh++) {
                        float* d0 = acc[mh][j2 * 2 + 0];
                        asm volatile(
                            "mma.sync.aligned.m16n8k16.row.col.f32.f16.f16.f32 "
                            "{%0,%1,%2,%3}, {%4,%5,%6,%7}, {%8,%9}, {%0,%1,%2,%3};"
                            : "+f"(d0[0]), "+f"(d0[1]), "+f"(d0[2]), "+f"(d0[3])
                            : "r"(a[mh][0]), "r"(a[mh][1]), "r"(a[mh][2]), "r"(a[mh][3]),
                              "r"(b0), "r"(b1));
                        float* d1 = acc[mh][j2 * 2 + 1];
                        asm volatile(
                            "mma.sync.aligned.m16n8k16.row.col.f32.f16.f16.f32 "
                            "{%0,%1,%2,%3}, {%4,%5,%6,%7}, {%8,%9}, {%0,%1,%2,%3};"
                            : "+f"(d1[0]), "+f"(d1[1]), "+f"(d1[2]), "+f"(d1[3])
                            : "r"(a[mh][0]), "r"(a[mh][1]), "r"(a[mh][2]), "r"(a[mh][3]),
                              "r"(b2), "r"(b3));
                    }
                }
            }
        }
    }

    int r0 = lane >> 2, c0 = (lane & 3) * 2;
#pragma unroll
    for (int mh = 0; mh < 4; mh++) {
        int xbase = x0 + warp * 64 + mh * 16;
#pragma unroll
        for (int j = 0; j < 4; j++) {
            int oc0 = j * 8 + c0;
            float bs0 = __ldg(&bias[oc0]), bs1 = __ldg(&bias[oc0 + 1]);
            size_t p0 = (((size_t)b * 32 + oc0)     * H + y) * W;
            size_t p1 = (((size_t)b * 32 + oc0 + 1) * H + y) * W;
            out[p0 + xbase + r0]     = fmaxf(acc[mh][j][0] + bs0, 0.0f);
            out[p1 + xbase + r0]     = fmaxf(acc[mh][j][1] + bs1, 0.0f);
            out[p0 + xbase + r0 + 8] = fmaxf(acc[mh][j][2] + bs0, 0.0f);
            out[p1 + xbase + r0 + 8] = fmaxf(acc[mh][j][3] + bs1, 0.0f);
        }
    }
}

// ---------------------------------------------------------------------------
// conv3: 5x5, IC=32 -> OC=1. 128x8 px tile, 4 px/thread (proven R8 version).
// ---------------------------------------------------------------------------
__global__ __launch_bounds__(256)
void conv3_kernel(const float* __restrict__ in, const float* __restrict__ w,
                  const float* __restrict__ bias, float* __restrict__ out,
                  int H, int W)
{
    const int ICC = 4, IC = 32;
    __shared__ __align__(16) float in_s[ICC][12][132];
    __shared__ float w_s[IC][25];

    int b  = blockIdx.z;
    int x0 = blockIdx.x * 128;
    int y0 = blockIdx.y * 8;
    int tid = threadIdx.x;
    int sx = tid & 31, sy = tid >> 5;

    for (int t = tid; t < IC * 25; t += 256) w_s[t / 25][t % 25] = w[t];

    float acc[4] = {0.f, 0.f, 0.f, 0.f};
    for (int cc = 0; cc < IC; cc += ICC) {
        __syncthreads();
        for (int t = tid; t < ICC * 12 * 132; t += 256) {
            int ic  = t / (12 * 132);
            int rem = t - ic * (12 * 132);
            int r = rem / 132, c = rem - r * 132;
            int gy = y0 - 2 + r, gx = x0 - 2 + c;
            float v = 0.f;
            if (gy >= 0 && gy < H && gx >= 0 && gx < W)
                v = in[((size_t)(b * IC + cc + ic) * H + gy) * W + gx];
            in_s[ic][r][c] = v;
        }
        __syncthreads();
#pragma unroll
        for (int ic = 0; ic < ICC; ic++) {
#pragma unroll
            for (int dy = 0; dy < 5; dy++) {
                const float* row = &in_s[ic][sy + dy][sx * 4];
                float4 Av = *(const float4*)row;
                float4 Bv = *(const float4*)(row + 4);
                float c8 = row[8];
                float v[9] = {Av.x, Av.y, Av.z, Av.w, Bv.x, Bv.y, Bv.z, Bv.w, c8};
                const float* wr = &w_s[cc + ic][dy * 5];
#pragma unroll
                for (int dx = 0; dx < 5; dx++) {
                    float wv = wr[dx];
#pragma unroll
                    for (int q = 0; q < 4; q++)
                        acc[q] = fmaf(v[dx + q], wv, acc[q]);
                }
            }
        }
    }

    int yy = y0 + sy;
    if (yy < H) {
#pragma unroll
        for (int q = 0; q < 4; q++) {
            int xx = x0 + sx * 4 + q;
            if (xx < W)
                out[((size_t)b * H + yy) * W + xx] = acc[q] + bias[0];
        }
    }
}

// ---------------------------------------------------------------------------
// Orchestration
// ---------------------------------------------------------------------------
extern "C" void kernel_launch(void* const* d_in, const int* in_sizes, int n_in,
                              void* d_out, int out_size)
{
    const float* x        = (const float*)d_in[0];
    const float* elev0    = (const float*)d_in[1];
    const float* elev1    = (const float*)d_in[2];
    const int*   psi_idx1 = (const int*)  d_in[3];
    const float* psi_val1 = (const float*)d_in[4];
    const float* w1       = (const float*)d_in[5];
    const float* b1       = (const float*)d_in[6];
    const float* cw2_1    = (const float*)d_in[7];
    const float* cb2_1    = (const float*)d_in[8];
    const float* cw3_1    = (const float*)d_in[9];
    const float* cb3_1    = (const float*)d_in[10];
    const int*   psi_idx2 = (const int*)  d_in[11];
    const float* psi_val2 = (const float*)d_in[12];
    const float* w2       = (const float*)d_in[13];
    const float* b2       = (const float*)d_in[14];
    const float* cw2_2    = (const float*)d_in[15];
    const float* cb2_2    = (const float*)d_in[16];
    const float* cw3_2    = (const float*)d_in[17];
    const float* cb3_2    = (const float*)d_in[18];
    float* out = (float*)d_out;

    float* scratch = nullptr;
    cudaGetSymbolAddress((void**)&scratch, g_scratch);
    __half* nhwcH = (__half*)(scratch + OFF_NHWCH);
    float*  bufB2 = scratch + OFF_B2;
    float*  bufH  = scratch + OFF_H;
    float*  bufY1 = scratch + OFF_Y1;
    __half* bufWH = (__half*)(scratch + OFF_WH);

    const int SMEM2 = (128 + 4) * 128 + 25600;   // NW=2: 42496
    const int SMEM4 = (256 + 4) * 128 + 25600;   // NW=4: 58880
    cudaFuncSetAttribute(conv2_mma<2>, cudaFuncAttributeMaxDynamicSharedMemorySize, SMEM2);
    cudaFuncSetAttribute(conv2_mma<4>, cudaFuncAttributeMaxDynamicSharedMemorySize, SMEM4);

    // ---------------- stage 1: 90x180 -> 180x360 ----------------
    {
        const int H = 180, W = 360, P = H * W, Hp = H + 4, Wp = W + 4;
        int total = B_ * H * W;
        int nbMain = (P + 255) / 256;
        int perB = 4 * Wp + (Hp - 4) * 4;
        int nbBorder = (B_ * perB + 255) / 256;
        upsample_concat_kernel<<<(total + 255) / 256, 256>>>(x, elev0, bufH, 90, 180);
        disco_kernel<<<nbMain + nbBorder, 256>>>(bufH, psi_idx1, psi_val1, w1, b1,
                                                 nhwcH, P, W, Hp, Wp, nbMain);
        wtransform_kernel<<<200, 256>>>(cw2_1, bufWH);
        dim3 g2((W + 127) / 128, H, B_);
        conv2_mma<2><<<g2, 64, SMEM2>>>(nhwcH, bufWH, cb2_1, bufB2, H, W);
        dim3 g3((W + 127) / 128, (H + 7) / 8, B_);
        conv3_kernel<<<g3, 256>>>(bufB2, cw3_1, cb3_1, bufY1, H, W);
    }
    // ---------------- stage 2: 180x360 -> 360x720 ----------------
    {
        const int H = 360, W = 720, P = H * W, Hp = H + 4, Wp = W + 4;
        int total = B_ * H * W;
        int nbMain = (P + 255) / 256;
        int perB = 4 * Wp + (Hp - 4) * 4;
        int nbBorder = (B_ * perB + 255) / 256;
        upsample_concat_kernel<<<(total + 255) / 256, 256>>>(bufY1, elev1, bufH, 180, 360);
        disco_kernel<<<nbMain + nbBorder, 256>>>(bufH, psi_idx2, psi_val2, w2, b2,
                                                 nhwcH, P, W, Hp, Wp, nbMain);
        wtransform_kernel<<<200, 256>>>(cw2_2, bufWH);
        dim3 g2((W + 255) / 256, H, B_);
        conv2_mma<4><<<g2, 128, SMEM4>>>(nhwcH, bufWH, cb2_2, bufB2, H, W);
        dim3 g3((W + 127) / 128, (H + 7) / 8, B_);
        conv3_kernel<<<g3, 256>>>(bufB2, cw3_2, cb3_2, out, H, W);
    }
}

// round 12
// speedup vs baseline: 2.6961x; 1.1068x over previous
#include <cuda_runtime.h>
#include <cuda_fp16.h>
#include <cstdint>
#include <cstddef>

// ===========================================================================
// DeepSDSphere R12: disco einsum moved to tensor cores (z[18] per px -> fp16
// smem A-tile, wq[32x64] fp16 B-tile, m16n8k16 MMA). conv2/conv3 = R11.
// ===========================================================================

#define B_   4
#define F_   64

// ---------------- scratch layout (floats) -----------------------------------
#define SZ_NHWCH (4ull*364ull*724ull*64ull/2ull)   // fp16 NHWC as float count
#define SZ_B2    (4ull*32ull*360ull*720ull)
#define SZ_H     (4ull*2ull*360ull*720ull)
#define SZ_Y1    (4ull*180ull*360ull)
#define SZ_WH    (25ull*64ull*32ull/2ull)          // conv2 fp16 weights
#define SZ_WQ    (1024ull)                         // disco fp16 weights (2048 halves)
#define OFF_NHWCH 0ull
#define OFF_B2    (OFF_NHWCH + SZ_NHWCH)
#define OFF_H     (OFF_B2 + SZ_B2)
#define OFF_Y1    (OFF_H + SZ_H)
#define OFF_WH    (OFF_Y1 + SZ_Y1)
#define OFF_WQ    (OFF_WH + SZ_WH)
#define SCRATCH_FLOATS (OFF_WQ + SZ_WQ)

__device__ __align__(1024) float g_scratch[SCRATCH_FLOATS];

__device__ __forceinline__ uint32_t smem_u32(const void* p) {
    uint32_t a;
    asm("{ .reg .u64 t; cvta.to.shared.u64 t, %1; cvt.u32.u64 %0, t; }"
        : "=r"(a) : "l"(p));
    return a;
}

// ---------------------------------------------------------------------------
// bilinear 2x upsample (half-pixel) + concat -> (B,2,H2,W2) NCHW fp32
// ---------------------------------------------------------------------------
__global__ void upsample_concat_kernel(const float* __restrict__ x,
                                       const float* __restrict__ elev,
                                       float* __restrict__ out,
                                       int Hin, int Win)
{
    int H2 = Hin * 2, W2 = Win * 2;
    int total = B_ * H2 * W2;
    int idx = blockIdx.x * blockDim.x + threadIdx.x;
    if (idx >= total) return;
    int j = idx % W2;
    int t = idx / W2;
    int i = t % H2;
    int b = t / H2;

    float sy = (i + 0.5f) * 0.5f - 0.5f;
    sy = fminf(fmaxf(sy, 0.0f), (float)(Hin - 1));
    int r0 = (int)floorf(sy);
    int r1 = min(r0 + 1, Hin - 1);
    float ty = sy - (float)r0;

    float sx = (j + 0.5f) * 0.5f - 0.5f;
    sx = fminf(fmaxf(sx, 0.0f), (float)(Win - 1));
    int c0 = (int)floorf(sx);
    int c1 = min(c0 + 1, Win - 1);
    float tx = sx - (float)c0;

    const float* xb = x + (size_t)b * Hin * Win;
    float v00 = xb[r0 * Win + c0];
    float v01 = xb[r0 * Win + c1];
    float v10 = xb[r1 * Win + c0];
    float v11 = xb[r1 * Win + c1];
    float left  = v00 * (1.0f - ty) + v10 * ty;
    float right = v01 * (1.0f - ty) + v11 * ty;
    float v = left * (1.0f - tx) + right * tx;

    size_t plane = (size_t)H2 * W2;
    out[((size_t)b * 2 + 0) * plane + (size_t)i * W2 + j] = v;
    out[((size_t)b * 2 + 1) * plane + (size_t)i * W2 + j] =
        elev[(size_t)b * plane + (size_t)i * W2 + j];
}

// ---------------------------------------------------------------------------
// disco weight transform: w (64oc, 2c, 9k) fp32 -> wq [32k][64oc] fp16
// (k = c*9+kk, rows 18..31 zero)
// ---------------------------------------------------------------------------
__global__ void wq_transform(const float* __restrict__ w,
                             __half* __restrict__ wq)
{
    int i = blockIdx.x * 256 + threadIdx.x;
    if (i >= 32 * 64) return;
    int k = i >> 6, oc = i & 63;
    float v = (k < 18) ? w[oc * 18 + k] : 0.0f;
    wq[i] = __float2half_rn(v);
}

// ---------------------------------------------------------------------------
// disco conv + bias + relu -> padded NHWC fp16, tensor-core einsum.
// Block = 128 threads (4 warps), 128 consecutive pixels.
// Phase 1: z[18] fp32 per px per batch -> fp16 smem rows (80B stride).
// Phase 2: per batch, [128x32] x [32x64] MMA, bias+relu+fp16 NHWC store.
// Border-zero blocks appended after nbMain (128 threads each).
// ---------------------------------------------------------------------------
__global__ __launch_bounds__(128)
void disco_mma(const float* __restrict__ h,
               const int*   __restrict__ idx,
               const float* __restrict__ val,
               const __half* __restrict__ wq,
               const float* __restrict__ bias,
               __half* __restrict__ nhwc,
               int P, int W, int Hp, int Wp, int nbMain)
{
    if (blockIdx.x >= nbMain) {
        int perB = 4 * Wp + (Hp - 4) * 4;
        int bi = (blockIdx.x - nbMain) * 128 + threadIdx.x;
        if (bi >= B_ * perB) return;
        int b = bi / perB;
        int r = bi % perB;
        int y, x;
        if (r < 2 * Wp)      { y = r / Wp;            x = r % Wp; }
        else if (r < 4 * Wp) { int r2 = r - 2 * Wp;   y = Hp - 2 + r2 / Wp; x = r2 % Wp; }
        else {
            int r3 = r - 4 * Wp;
            int side = r3 & 3;
            y = 2 + (r3 >> 2);
            x = (side < 2) ? side : (Wp - 4 + side);
        }
        uint4 z = make_uint4(0, 0, 0, 0);
        uint4* p = (uint4*)(nhwc + (((size_t)b * Hp + y) * Wp + x) * 64);
#pragma unroll
        for (int k = 0; k < 8; k++) p[k] = z;
        return;
    }

    __shared__ __align__(16) char zsm[4 * 128 * 80];   // 40,960 B (z tiles, 4 batches)
    __shared__ __align__(16) char bsm[32 * 128];        //  4,096 B (wq tile)

    int tid = threadIdx.x;
    int warp = tid >> 5, lane = tid & 31;
    uint32_t zs_b = smem_u32(zsm);
    uint32_t bs_b = smem_u32(bsm);

    // stage B tile: 32 k-rows x 128B, conv2-style XOR swizzle
    for (int i = tid; i < 256; i += 128) {
        int k = i >> 3, g = i & 7;
        *(uint4*)(bsm + k * 128 + ((g ^ (k & 7)) << 4)) = ((const uint4*)wq)[i];
    }

    int p = blockIdx.x * 128 + tid;
    bool valid = p < P;
    int pc = valid ? p : (P - 1);

    int id[8];
    const int4* ip = reinterpret_cast<const int4*>(idx + (size_t)pc * 8);
    int4 ia = ip[0], ib4 = ip[1];
    id[0]=ia.x; id[1]=ia.y; id[2]=ia.z; id[3]=ia.w;
    id[4]=ib4.x; id[5]=ib4.y; id[6]=ib4.z; id[7]=ib4.w;

    float v[9][8];
#pragma unroll
    for (int k = 0; k < 9; k++) {
        const float4* vp = reinterpret_cast<const float4*>(val + ((size_t)k * P + pc) * 8);
        float4 a = vp[0], c = vp[1];
        v[k][0]=a.x; v[k][1]=a.y; v[k][2]=a.z; v[k][3]=a.w;
        v[k][4]=c.x; v[k][5]=c.y; v[k][6]=c.z; v[k][7]=c.w;
    }

    // Phase 1: z for all 4 batches -> fp16 smem rows
    for (int b = 0; b < B_; b++) {
        uint32_t rowbuf[20];
        __half* hb = (__half*)rowbuf;
#pragma unroll
        for (int q = 18; q < 40; q++) hb[q] = __ushort_as_half(0);
        if (valid) {
            const float* h0 = h + (size_t)(b * 2 + 0) * P;
            const float* h1 = h + (size_t)(b * 2 + 1) * P;
            float g0[8], g1[8];
#pragma unroll
            for (int n = 0; n < 8; n++) { g0[n] = h0[id[n]]; g1[n] = h1[id[n]]; }
#pragma unroll
            for (int k = 0; k < 9; k++) {
                float s0 = 0.0f, s1 = 0.0f;
#pragma unroll
                for (int n = 0; n < 8; n++) {
                    s0 = fmaf(g0[n], v[k][n], s0);
                    s1 = fmaf(g1[n], v[k][n], s1);
                }
                hb[k]     = __float2half_rn(s0);
                hb[9 + k] = __float2half_rn(s1);
            }
        } else {
#pragma unroll
            for (int q = 0; q < 18; q++) hb[q] = __ushort_as_half(0);
        }
        uint4* dst = (uint4*)(zsm + b * (128 * 80) + tid * 80);
        uint4* src = (uint4*)rowbuf;
#pragma unroll
        for (int i = 0; i < 5; i++) dst[i] = src[i];
    }
    __syncthreads();

    // Phase 2: per batch, warp computes M=32 (2 m-tiles) x N=64
    for (int b = 0; b < B_; b++) {
        float acc[2][8][4];
#pragma unroll
        for (int m = 0; m < 2; m++)
#pragma unroll
            for (int j = 0; j < 8; j++)
#pragma unroll
                for (int q = 0; q < 4; q++) acc[m][j][q] = 0.0f;

        uint32_t zbase = zs_b + b * (128 * 80);
#pragma unroll
        for (int ks = 0; ks < 2; ks++) {
            uint32_t a[2][4];
#pragma unroll
            for (int mh = 0; mh < 2; mh++) {
                int r = warp * 32 + mh * 16 + (lane & 15);
                int g = ks * 2 + (lane >> 4);
                uint32_t addr = zbase + r * 80 + g * 16;
                asm volatile(
                    "ldmatrix.sync.aligned.m8n8.x4.shared.b16 {%0,%1,%2,%3}, [%4];"
                    : "=r"(a[mh][0]), "=r"(a[mh][1]), "=r"(a[mh][2]), "=r"(a[mh][3])
                    : "r"(addr));
            }
#pragma unroll
            for (int jp = 0; jp < 4; jp++) {
                uint32_t b0, b1, b2, b3;
                {
                    int k = ks * 16 + (lane & 15);
                    int g = jp * 2 + (lane >> 4);
                    uint32_t addr = bs_b + k * 128 + ((g ^ (k & 7)) << 4);
                    asm volatile(
                        "ldmatrix.sync.aligned.m8n8.x4.trans.shared.b16 {%0,%1,%2,%3}, [%4];"
                        : "=r"(b0), "=r"(b1), "=r"(b2), "=r"(b3) : "r"(addr));
                }
#pragma unroll
                for (int mh = 0; mh < 2; mh++) {
                    float* d0 = acc[mh][jp * 2 + 0];
                    asm volatile(
                        "mma.sync.aligned.m16n8k16.row.col.f32.f16.f16.f32 "
                        "{%0,%1,%2,%3}, {%4,%5,%6,%7}, {%8,%9}, {%0,%1,%2,%3};"
                        : "+f"(d0[0]), "+f"(d0[1]), "+f"(d0[2]), "+f"(d0[3])
                        : "r"(a[mh][0]), "r"(a[mh][1]), "r"(a[mh][2]), "r"(a[mh][3]),
                          "r"(b0), "r"(b1));
                    float* d1 = acc[mh][jp * 2 + 1];
                    asm volatile(
                        "mma.sync.aligned.m16n8k16.row.col.f32.f16.f16.f32 "
                        "{%0,%1,%2,%3}, {%4,%5,%6,%7}, {%8,%9}, {%0,%1,%2,%3};"
                        : "+f"(d1[0]), "+f"(d1[1]), "+f"(d1[2]), "+f"(d1[3])
                        : "r"(a[mh][0]), "r"(a[mh][1]), "r"(a[mh][2]), "r"(a[mh][3]),
                          "r"(b2), "r"(b3));
                }
            }
        }

        // epilogue: bias + relu + fp16 store to padded NHWC
        int r0 = lane >> 2, c0 = (lane & 3) * 2;
#pragma unroll
        for (int mh = 0; mh < 2; mh++) {
            int mbase = warp * 32 + mh * 16;
#pragma unroll
            for (int rr = 0; rr < 2; rr++) {
                int pp = blockIdx.x * 128 + mbase + r0 + rr * 8;
                if (pp < P) {
                    int py = pp / W, px = pp - py * W;
                    __half* op = nhwc + (((size_t)b * Hp + (py + 2)) * Wp + (px + 2)) * 64;
#pragma unroll
                    for (int j = 0; j < 8; j++) {
                        int oc = j * 8 + c0;
                        float v0 = acc[mh][j][rr * 2 + 0] + __ldg(&bias[oc]);
                        float v1 = acc[mh][j][rr * 2 + 1] + __ldg(&bias[oc + 1]);
                        __half2 hv = __floats2half2_rn(fmaxf(v0, 0.0f), fmaxf(v1, 0.0f));
                        *(__half2*)(op + oc) = hv;
                    }
                }
            }
        }
    }
}

// ---------------------------------------------------------------------------
// conv2 weight transform: (32oc,64ic,5,5) fp32 -> fp16 [tap][ic][oc]
// ---------------------------------------------------------------------------
__global__ void wtransform_kernel(const float* __restrict__ w,
                                  __half* __restrict__ wh)
{
    int i = blockIdx.x * 256 + threadIdx.x;
    if (i >= 25 * 64 * 32) return;
    int tap = i / 2048;
    int r = i % 2048;
    int ic = r >> 5;
    int oc = r & 31;
    wh[i] = __float2half_rn(w[((size_t)oc * 64 + ic) * 25 + tap]);
}

// ---------------------------------------------------------------------------
// conv2 via warp-level fp16 mma, warp M=64, NW warps/block (proven R11)
// ---------------------------------------------------------------------------
template<int NW>
__global__ __launch_bounds__(NW * 32)
void conv2_mma(const __half* __restrict__ nhwc, const __half* __restrict__ wh,
               const float* __restrict__ bias, float* __restrict__ out,
               int H, int W)
{
    constexpr int TW = NW * 64;
    constexpr int A_BYTES = (TW + 4) * 128;
    extern __shared__ __align__(16) char sm[];
    char* As = sm;
    char* Bs = sm + A_BYTES;

    const int Hp = H + 4, Wp = W + 4;
    int b = blockIdx.z, y = blockIdx.y;
    int x0 = blockIdx.x * TW;
    if (x0 > W - TW) x0 = W - TW;
    int tid = threadIdx.x;
    int warp = tid >> 5, lane = tid & 31;

    uint32_t As_b = smem_u32(As);
    uint32_t Bs_b = smem_u32(Bs);

    float acc[4][4][4];
#pragma unroll
    for (int m = 0; m < 4; m++)
#pragma unroll
        for (int j = 0; j < 4; j++)
#pragma unroll
            for (int q = 0; q < 4; q++) acc[m][j][q] = 0.0f;

    for (int dy = 0; dy < 5; dy++) {
        __syncthreads();
        const uint4* srcA = (const uint4*)(nhwc +
            ((size_t)(b * Hp + y + dy) * Wp + x0) * 64);
        for (int i = tid; i < (TW + 4) * 8; i += NW * 32) {
            int p = i >> 3, g = i & 7;
            *(uint4*)(As + p * 128 + ((g ^ (p & 7)) << 4)) = srcA[i];
        }
        const uint4* srcB = (const uint4*)(wh + (size_t)dy * 5 * 2048);
        for (int i = tid; i < 1280; i += NW * 32) {
            int tap5 = i >> 8, k = (i >> 2) & 63, g = i & 3;
            *(uint4*)(Bs + tap5 * 5120 + k * 80 + g * 16) = srcB[i];
        }
        __syncthreads();

#pragma unroll
        for (int dx = 0; dx < 5; dx++) {
#pragma unroll
            for (int ks = 0; ks < 4; ks++) {
                uint32_t a[4][4];
#pragma unroll
                for (int mh = 0; mh < 4; mh++) {
                    int r = warp * 64 + mh * 16 + dx + (lane & 15);
                    int g = ks * 2 + (lane >> 4);
                    uint32_t addr = As_b + r * 128 + ((g ^ (r & 7)) << 4);
                    asm volatile(
                        "ldmatrix.sync.aligned.m8n8.x4.shared.b16 {%0,%1,%2,%3}, [%4];"
                        : "=r"(a[mh][0]), "=r"(a[mh][1]), "=r"(a[mh][2]), "=r"(a[mh][3])
                        : "r"(addr));
                }
#pragma unroll
                for (int j2 = 0; j2 < 2; j2++) {
                    uint32_t b0, b1, b2, b3;
                    {
                        int k = ks * 16 + (lane & 15);
                        int g = j2 * 2 + (lane >> 4);
                        uint32_t addr = Bs_b + dx * 5120 + k * 80 + g * 16;
                        asm volatile(
                            "ldmatrix.sync.aligned.m8n8.x4.trans.shared.b16 {%0,%1,%2,%3}, [%4];"
                            : "=r"(b0), "=r"(b1), "=r"(b2), "=r"(b3) : "r"(addr));
                    }
#pragma unroll
                    for (int mh = 0; mh < 4; mh++) {
                        float* d0 = acc[mh][j2 * 2 + 0];
                        asm volatile(
                            "mma.sync.aligned.m16n8k16.row.col.f32.f16.f16.f32 "
                            "{%0,%1,%2,%3}, {%4,%5,%6,%7}, {%8,%9}, {%0,%1,%2,%3};"
                            : "+f"(d0[0]), "+f"(d0[1]), "+f"(d0[2]), "+f"(d0[3])
                            : "r"(a[mh][0]), "r"(a[mh][1]), "r"(a[mh][2]), "r"(a[mh][3]),
                              "r"(b0), "r"(b1));
                        float* d1 = acc[mh][j2 * 2 + 1];
                        asm volatile(
                            "mma.sync.aligned.m16n8k16.row.col.f32.f16.f16.f32 "
                            "{%0,%1,%2,%3}, {%4,%5,%6,%7}, {%8,%9}, {%0,%1,%2,%3};"
                            : "+f"(d1[0]), "+f"(d1[1]), "+f"(d1[2]), "+f"(d1[3])
                            : "r"(a[mh][0]), "r"(a[mh][1]), "r"(a[mh][2]), "r"(a[mh][3]),
                              "r"(b2), "r"(b3));
                    }
                }
            }
        }
    }

    int r0 = lane >> 2, c0 = (lane & 3) * 2;
#pragma unroll
    for (int mh = 0; mh < 4; mh++) {
        int xbase = x0 + warp * 64 + mh * 16;
#pragma unroll
        for (int j = 0; j < 4; j++) {
            int oc0 = j * 8 + c0;
            float bs0 = __ldg(&bias[oc0]), bs1 = __ldg(&bias[oc0 + 1]);
            size_t p0 = (((size_t)b * 32 + oc0)     * H + y) * W;
            size_t p1 = (((size_t)b * 32 + oc0 + 1) * H + y) * W;
            out[p0 + xbase + r0]     = fmaxf(acc[mh][j][0] + bs0, 0.0f);
            out[p1 + xbase + r0]     = fmaxf(acc[mh][j][1] + bs1, 0.0f);
            out[p0 + xbase + r0 + 8] = fmaxf(acc[mh][j][2] + bs0, 0.0f);
            out[p1 + xbase + r0 + 8] = fmaxf(acc[mh][j][3] + bs1, 0.0f);
        }
    }
}

// ---------------------------------------------------------------------------
// conv3: 5x5, IC=32 -> OC=1. 128x8 px tile, 4 px/thread (proven R8 version).
// ---------------------------------------------------------------------------
__global__ __launch_bounds__(256)
void conv3_kernel(const float* __restrict__ in, const float* __restrict__ w,
                  const float* __restrict__ bias, float* __restrict__ out,
                  int H, int W)
{
    const int ICC = 4, IC = 32;
    __shared__ __align__(16) float in_s[ICC][12][132];
    __shared__ float w_s[IC][25];

    int b  = blockIdx.z;
    int x0 = blockIdx.x * 128;
    int y0 = blockIdx.y * 8;
    int tid = threadIdx.x;
    int sx = tid & 31, sy = tid >> 5;

    for (int t = tid; t < IC * 25; t += 256) w_s[t / 25][t % 25] = w[t];

    float acc[4] = {0.f, 0.f, 0.f, 0.f};
    for (int cc = 0; cc < IC; cc += ICC) {
        __syncthreads();
        for (int t = tid; t < ICC * 12 * 132; t += 256) {
            int ic  = t / (12 * 132);
            int rem = t - ic * (12 * 132);
            int r = rem / 132, c = rem - r * 132;
            int gy = y0 - 2 + r, gx = x0 - 2 + c;
            float v = 0.f;
            if (gy >= 0 && gy < H && gx >= 0 && gx < W)
                v = in[((size_t)(b * IC + cc + ic) * H + gy) * W + gx];
            in_s[ic][r][c] = v;
        }
        __syncthreads();
#pragma unroll
        for (int ic = 0; ic < ICC; ic++) {
#pragma unroll
            for (int dy = 0; dy < 5; dy++) {
                const float* row = &in_s[ic][sy + dy][sx * 4];
                float4 Av = *(const float4*)row;
                float4 Bv = *(const float4*)(row + 4);
                float c8 = row[8];
                float v[9] = {Av.x, Av.y, Av.z, Av.w, Bv.x, Bv.y, Bv.z, Bv.w, c8};
                const float* wr = &w_s[cc + ic][dy * 5];
#pragma unroll
                for (int dx = 0; dx < 5; dx++) {
                    float wv = wr[dx];
#pragma unroll
                    for (int q = 0; q < 4; q++)
                        acc[q] = fmaf(v[dx + q], wv, acc[q]);
                }
            }
        }
    }

    int yy = y0 + sy;
    if (yy < H) {
#pragma unroll
        for (int q = 0; q < 4; q++) {
            int xx = x0 + sx * 4 + q;
            if (xx < W)
                out[((size_t)b * H + yy) * W + xx] = acc[q] + bias[0];
        }
    }
}

// ---------------------------------------------------------------------------
// Orchestration
// ---------------------------------------------------------------------------
extern "C" void kernel_launch(void* const* d_in, const int* in_sizes, int n_in,
                              void* d_out, int out_size)
{
    const float* x        = (const float*)d_in[0];
    const float* elev0    = (const float*)d_in[1];
    const float* elev1    = (const float*)d_in[2];
    const int*   psi_idx1 = (const int*)  d_in[3];
    const float* psi_val1 = (const float*)d_in[4];
    const float* w1       = (const float*)d_in[5];
    const float* b1       = (const float*)d_in[6];
    const float* cw2_1    = (const float*)d_in[7];
    const float* cb2_1    = (const float*)d_in[8];
    const float* cw3_1    = (const float*)d_in[9];
    const float* cb3_1    = (const float*)d_in[10];
    const int*   psi_idx2 = (const int*)  d_in[11];
    const float* psi_val2 = (const float*)d_in[12];
    const float* w2       = (const float*)d_in[13];
    const float* b2       = (const float*)d_in[14];
    const float* cw2_2    = (const float*)d_in[15];
    const float* cb2_2    = (const float*)d_in[16];
    const float* cw3_2    = (const float*)d_in[17];
    const float* cb3_2    = (const float*)d_in[18];
    float* out = (float*)d_out;

    float* scratch = nullptr;
    cudaGetSymbolAddress((void**)&scratch, g_scratch);
    __half* nhwcH = (__half*)(scratch + OFF_NHWCH);
    float*  bufB2 = scratch + OFF_B2;
    float*  bufH  = scratch + OFF_H;
    float*  bufY1 = scratch + OFF_Y1;
    __half* bufWH = (__half*)(scratch + OFF_WH);
    __half* bufWQ = (__half*)(scratch + OFF_WQ);

    const int SMEM2 = (128 + 4) * 128 + 25600;   // NW=2: 42496
    const int SMEM4 = (256 + 4) * 128 + 25600;   // NW=4: 58880
    cudaFuncSetAttribute(conv2_mma<2>, cudaFuncAttributeMaxDynamicSharedMemorySize, SMEM2);
    cudaFuncSetAttribute(conv2_mma<4>, cudaFuncAttributeMaxDynamicSharedMemorySize, SMEM4);

    // ---------------- stage 1: 90x180 -> 180x360 ----------------
    {
        const int H = 180, W = 360, P = H * W, Hp = H + 4, Wp = W + 4;
        int total = B_ * H * W;
        int nbMain = (P + 127) / 128;
        int perB = 4 * Wp + (Hp - 4) * 4;
        int nbBorder = (B_ * perB + 127) / 128;
        upsample_concat_kernel<<<(total + 255) / 256, 256>>>(x, elev0, bufH, 90, 180);
        wq_transform<<<8, 256>>>(w1, bufWQ);
        disco_mma<<<nbMain + nbBorder, 128>>>(bufH, psi_idx1, psi_val1, bufWQ, b1,
                                              nhwcH, P, W, Hp, Wp, nbMain);
        wtransform_kernel<<<200, 256>>>(cw2_1, bufWH);
        dim3 g2((W + 127) / 128, H, B_);
        conv2_mma<2><<<g2, 64, SMEM2>>>(nhwcH, bufWH, cb2_1, bufB2, H, W);
        dim3 g3((W + 127) / 128, (H + 7) / 8, B_);
        conv3_kernel<<<g3, 256>>>(bufB2, cw3_1, cb3_1, bufY1, H, W);
    }
    // ---------------- stage 2: 180x360 -> 360x720 ----------------
    {
        const int H = 360, W = 720, P = H * W, Hp = H + 4, Wp = W + 4;
        int total = B_ * H * W;
        int nbMain = (P + 127) / 128;
        int perB = 4 * Wp + (Hp - 4) * 4;
        int nbBorder = (B_ * perB + 127) / 128;
        upsample_concat_kernel<<<(total + 255) / 256, 256>>>(bufY1, elev1, bufH, 180, 360);
        wq_transform<<<8, 256>>>(w2, bufWQ);
        disco_mma<<<nbMain + nbBorder, 128>>>(bufH, psi_idx2, psi_val2, bufWQ, b2,
                                              nhwcH, P, W, Hp, Wp, nbMain);
        wtransform_kernel<<<200, 256>>>(cw2_2, bufWH);
        dim3 g2((W + 255) / 256, H, B_);
        conv2_mma<4><<<g2, 128, SMEM4>>>(nhwcH, bufWH, cb2_2, bufB2, H, W);
        dim3 g3((W + 127) / 128, (H + 7) / 8, B_);
        conv3_kernel<<<g3, 256>>>(bufB2, cw3_2, cb3_2, out, H, W);
    }
}

// round 13
// speedup vs baseline: 2.7626x; 1.0247x over previous
#include <cuda_runtime.h>
#include <cuda_fp16.h>
#include <cstdint>
#include <cstddef>

// ===========================================================================
// DeepSDSphere R13: conv2 smem diet — B tile compacted 80B->64B rows with
// XOR-((k>>1)&3) swizzle (conflict-free LDSM), raising residency
// (NW=2: 5->6 blocks/SM, NW=4: 3->4 via launch_bounds). Rest = R12.
// ===========================================================================

#define B_   4
#define F_   64

// ---------------- scratch layout (floats) -----------------------------------
#define SZ_NHWCH (4ull*364ull*724ull*64ull/2ull)   // fp16 NHWC as float count
#define SZ_B2    (4ull*32ull*360ull*720ull)
#define SZ_H     (4ull*2ull*360ull*720ull)
#define SZ_Y1    (4ull*180ull*360ull)
#define SZ_WH    (25ull*64ull*32ull/2ull)          // conv2 fp16 weights
#define SZ_WQ    (1024ull)                         // disco fp16 weights
#define OFF_NHWCH 0ull
#define OFF_B2    (OFF_NHWCH + SZ_NHWCH)
#define OFF_H     (OFF_B2 + SZ_B2)
#define OFF_Y1    (OFF_H + SZ_H)
#define OFF_WH    (OFF_Y1 + SZ_Y1)
#define OFF_WQ    (OFF_WH + SZ_WH)
#define SCRATCH_FLOATS (OFF_WQ + SZ_WQ)

__device__ __align__(1024) float g_scratch[SCRATCH_FLOATS];

__device__ __forceinline__ uint32_t smem_u32(const void* p) {
    uint32_t a;
    asm("{ .reg .u64 t; cvta.to.shared.u64 t, %1; cvt.u32.u64 %0, t; }"
        : "=r"(a) : "l"(p));
    return a;
}

// ---------------------------------------------------------------------------
// bilinear 2x upsample (half-pixel) + concat -> (B,2,H2,W2) NCHW fp32
// ---------------------------------------------------------------------------
__global__ void upsample_concat_kernel(const float* __restrict__ x,
                                       const float* __restrict__ elev,
                                       float* __restrict__ out,
                                       int Hin, int Win)
{
    int H2 = Hin * 2, W2 = Win * 2;
    int total = B_ * H2 * W2;
    int idx = blockIdx.x * blockDim.x + threadIdx.x;
    if (idx >= total) return;
    int j = idx % W2;
    int t = idx / W2;
    int i = t % H2;
    int b = t / H2;

    float sy = (i + 0.5f) * 0.5f - 0.5f;
    sy = fminf(fmaxf(sy, 0.0f), (float)(Hin - 1));
    int r0 = (int)floorf(sy);
    int r1 = min(r0 + 1, Hin - 1);
    float ty = sy - (float)r0;

    float sx = (j + 0.5f) * 0.5f - 0.5f;
    sx = fminf(fmaxf(sx, 0.0f), (float)(Win - 1));
    int c0 = (int)floorf(sx);
    int c1 = min(c0 + 1, Win - 1);
    float tx = sx - (float)c0;

    const float* xb = x + (size_t)b * Hin * Win;
    float v00 = xb[r0 * Win + c0];
    float v01 = xb[r0 * Win + c1];
    float v10 = xb[r1 * Win + c0];
    float v11 = xb[r1 * Win + c1];
    float left  = v00 * (1.0f - ty) + v10 * ty;
    float right = v01 * (1.0f - ty) + v11 * ty;
    float v = left * (1.0f - tx) + right * tx;

    size_t plane = (size_t)H2 * W2;
    out[((size_t)b * 2 + 0) * plane + (size_t)i * W2 + j] = v;
    out[((size_t)b * 2 + 1) * plane + (size_t)i * W2 + j] =
        elev[(size_t)b * plane + (size_t)i * W2 + j];
}

// ---------------------------------------------------------------------------
// disco weight transform: w (64oc, 2c, 9k) fp32 -> wq [32k][64oc] fp16
// ---------------------------------------------------------------------------
__global__ void wq_transform(const float* __restrict__ w,
                             __half* __restrict__ wq)
{
    int i = blockIdx.x * 256 + threadIdx.x;
    if (i >= 32 * 64) return;
    int k = i >> 6, oc = i & 63;
    float v = (k < 18) ? w[oc * 18 + k] : 0.0f;
    wq[i] = __float2half_rn(v);
}

// ---------------------------------------------------------------------------
// disco conv + bias + relu -> padded NHWC fp16, tensor-core einsum (R12).
// ---------------------------------------------------------------------------
__global__ __launch_bounds__(128)
void disco_mma(const float* __restrict__ h,
               const int*   __restrict__ idx,
               const float* __restrict__ val,
               const __half* __restrict__ wq,
               const float* __restrict__ bias,
               __half* __restrict__ nhwc,
               int P, int W, int Hp, int Wp, int nbMain)
{
    if (blockIdx.x >= nbMain) {
        int perB = 4 * Wp + (Hp - 4) * 4;
        int bi = (blockIdx.x - nbMain) * 128 + threadIdx.x;
        if (bi >= B_ * perB) return;
        int b = bi / perB;
        int r = bi % perB;
        int y, x;
        if (r < 2 * Wp)      { y = r / Wp;            x = r % Wp; }
        else if (r < 4 * Wp) { int r2 = r - 2 * Wp;   y = Hp - 2 + r2 / Wp; x = r2 % Wp; }
        else {
            int r3 = r - 4 * Wp;
            int side = r3 & 3;
            y = 2 + (r3 >> 2);
            x = (side < 2) ? side : (Wp - 4 + side);
        }
        uint4 z = make_uint4(0, 0, 0, 0);
        uint4* p = (uint4*)(nhwc + (((size_t)b * Hp + y) * Wp + x) * 64);
#pragma unroll
        for (int k = 0; k < 8; k++) p[k] = z;
        return;
    }

    __shared__ __align__(16) char zsm[4 * 128 * 80];
    __shared__ __align__(16) char bsm[32 * 128];

    int tid = threadIdx.x;
    int warp = tid >> 5, lane = tid & 31;
    uint32_t zs_b = smem_u32(zsm);
    uint32_t bs_b = smem_u32(bsm);

    for (int i = tid; i < 256; i += 128) {
        int k = i >> 3, g = i & 7;
        *(uint4*)(bsm + k * 128 + ((g ^ (k & 7)) << 4)) = ((const uint4*)wq)[i];
    }

    int p = blockIdx.x * 128 + tid;
    bool valid = p < P;
    int pc = valid ? p : (P - 1);

    int id[8];
    const int4* ip = reinterpret_cast<const int4*>(idx + (size_t)pc * 8);
    int4 ia = ip[0], ib4 = ip[1];
    id[0]=ia.x; id[1]=ia.y; id[2]=ia.z; id[3]=ia.w;
    id[4]=ib4.x; id[5]=ib4.y; id[6]=ib4.z; id[7]=ib4.w;

    float v[9][8];
#pragma unroll
    for (int k = 0; k < 9; k++) {
        const float4* vp = reinterpret_cast<const float4*>(val + ((size_t)k * P + pc) * 8);
        float4 a = vp[0], c = vp[1];
        v[k][0]=a.x; v[k][1]=a.y; v[k][2]=a.z; v[k][3]=a.w;
        v[k][4]=c.x; v[k][5]=c.y; v[k][6]=c.z; v[k][7]=c.w;
    }

    for (int b = 0; b < B_; b++) {
        uint32_t rowbuf[20];
        __half* hb = (__half*)rowbuf;
#pragma unroll
        for (int q = 18; q < 40; q++) hb[q] = __ushort_as_half(0);
        if (valid) {
            const float* h0 = h + (size_t)(b * 2 + 0) * P;
            const float* h1 = h + (size_t)(b * 2 + 1) * P;
            float g0[8], g1[8];
#pragma unroll
            for (int n = 0; n < 8; n++) { g0[n] = h0[id[n]]; g1[n] = h1[id[n]]; }
#pragma unroll
            for (int k = 0; k < 9; k++) {
                float s0 = 0.0f, s1 = 0.0f;
#pragma unroll
                for (int n = 0; n < 8; n++) {
                    s0 = fmaf(g0[n], v[k][n], s0);
                    s1 = fmaf(g1[n], v[k][n], s1);
                }
                hb[k]     = __float2half_rn(s0);
                hb[9 + k] = __float2half_rn(s1);
            }
        } else {
#pragma unroll
            for (int q = 0; q < 18; q++) hb[q] = __ushort_as_half(0);
        }
        uint4* dst = (uint4*)(zsm + b * (128 * 80) + tid * 80);
        uint4* src = (uint4*)rowbuf;
#pragma unroll
        for (int i = 0; i < 5; i++) dst[i] = src[i];
    }
    __syncthreads();

    for (int b = 0; b < B_; b++) {
        float acc[2][8][4];
#pragma unroll
        for (int m = 0; m < 2; m++)
#pragma unroll
            for (int j = 0; j < 8; j++)
#pragma unroll
                for (int q = 0; q < 4; q++) acc[m][j][q] = 0.0f;

        uint32_t zbase = zs_b + b * (128 * 80);
#pragma unroll
        for (int ks = 0; ks < 2; ks++) {
            uint32_t a[2][4];
#pragma unroll
            for (int mh = 0; mh < 2; mh++) {
                int r = warp * 32 + mh * 16 + (lane & 15);
                int g = ks * 2 + (lane >> 4);
                uint32_t addr = zbase + r * 80 + g * 16;
                asm volatile(
                    "ldmatrix.sync.aligned.m8n8.x4.shared.b16 {%0,%1,%2,%3}, [%4];"
                    : "=r"(a[mh][0]), "=r"(a[mh][1]), "=r"(a[mh][2]), "=r"(a[mh][3])
                    : "r"(addr));
            }
#pragma unroll
            for (int jp = 0; jp < 4; jp++) {
                uint32_t b0, b1, b2, b3;
                {
                    int k = ks * 16 + (lane & 15);
                    int g = jp * 2 + (lane >> 4);
                    uint32_t addr = bs_b + k * 128 + ((g ^ (k & 7)) << 4);
                    asm volatile(
                        "ldmatrix.sync.aligned.m8n8.x4.trans.shared.b16 {%0,%1,%2,%3}, [%4];"
                        : "=r"(b0), "=r"(b1), "=r"(b2), "=r"(b3) : "r"(addr));
                }
#pragma unroll
                for (int mh = 0; mh < 2; mh++) {
                    float* d0 = acc[mh][jp * 2 + 0];
                    asm volatile(
                        "mma.sync.aligned.m16n8k16.row.col.f32.f16.f16.f32 "
                        "{%0,%1,%2,%3}, {%4,%5,%6,%7}, {%8,%9}, {%0,%1,%2,%3};"
                        : "+f"(d0[0]), "+f"(d0[1]), "+f"(d0[2]), "+f"(d0[3])
                        : "r"(a[mh][0]), "r"(a[mh][1]), "r"(a[mh][2]), "r"(a[mh][3]),
                          "r"(b0), "r"(b1));
                    float* d1 = acc[mh][jp * 2 + 1];
                    asm volatile(
                        "mma.sync.aligned.m16n8k16.row.col.f32.f16.f16.f32 "
                        "{%0,%1,%2,%3}, {%4,%5,%6,%7}, {%8,%9}, {%0,%1,%2,%3};"
                        : "+f"(d1[0]), "+f"(d1[1]), "+f"(d1[2]), "+f"(d1[3])
                        : "r"(a[mh][0]), "r"(a[mh][1]), "r"(a[mh][2]), "r"(a[mh][3]),
                          "r"(b2), "r"(b3));
                }
            }
        }

        int r0 = lane >> 2, c0 = (lane & 3) * 2;
#pragma unroll
        for (int mh = 0; mh < 2; mh++) {
            int mbase = warp * 32 + mh * 16;
#pragma unroll
            for (int rr = 0; rr < 2; rr++) {
                int pp = blockIdx.x * 128 + mbase + r0 + rr * 8;
                if (pp < P) {
                    int py = pp / W, px = pp - py * W;
                    __half* op = nhwc + (((size_t)b * Hp + (py + 2)) * Wp + (px + 2)) * 64;
#pragma unroll
                    for (int j = 0; j < 8; j++) {
                        int oc = j * 8 + c0;
                        float v0 = acc[mh][j][rr * 2 + 0] + __ldg(&bias[oc]);
                        float v1 = acc[mh][j][rr * 2 + 1] + __ldg(&bias[oc + 1]);
                        __half2 hv = __floats2half2_rn(fmaxf(v0, 0.0f), fmaxf(v1, 0.0f));
                        *(__half2*)(op + oc) = hv;
                    }
                }
            }
        }
    }
}

// ---------------------------------------------------------------------------
// conv2 weight transform: (32oc,64ic,5,5) fp32 -> fp16 [tap][ic][oc]
// ---------------------------------------------------------------------------
__global__ void wtransform_kernel(const float* __restrict__ w,
                                  __half* __restrict__ wh)
{
    int i = blockIdx.x * 256 + threadIdx.x;
    if (i >= 25 * 64 * 32) return;
    int tap = i / 2048;
    int r = i % 2048;
    int ic = r >> 5;
    int oc = r & 31;
    wh[i] = __float2half_rn(w[((size_t)oc * 64 + ic) * 25 + tap]);
}

// ---------------------------------------------------------------------------
// conv2 via warp-level fp16 mma, warp M=64, NW warps/block.
// R13: B tile 64B rows, XOR ((k>>1)&3) swizzle. smem: A (TW+4)*128 + B 20480.
// ---------------------------------------------------------------------------
template<int NW>
__global__ __launch_bounds__(NW * 32, (NW == 2) ? 6 : 4)
void conv2_mma(const __half* __restrict__ nhwc, const __half* __restrict__ wh,
               const float* __restrict__ bias, float* __restrict__ out,
               int H, int W)
{
    constexpr int TW = NW * 64;
    constexpr int A_BYTES = (TW + 4) * 128;
    extern __shared__ __align__(16) char sm[];
    char* As = sm;
    char* Bs = sm + A_BYTES;

    const int Hp = H + 4, Wp = W + 4;
    int b = blockIdx.z, y = blockIdx.y;
    int x0 = blockIdx.x * TW;
    if (x0 > W - TW) x0 = W - TW;
    int tid = threadIdx.x;
    int warp = tid >> 5, lane = tid & 31;

    uint32_t As_b = smem_u32(As);
    uint32_t Bs_b = smem_u32(Bs);

    float acc[4][4][4];
#pragma unroll
    for (int m = 0; m < 4; m++)
#pragma unroll
        for (int j = 0; j < 4; j++)
#pragma unroll
            for (int q = 0; q < 4; q++) acc[m][j][q] = 0.0f;

    for (int dy = 0; dy < 5; dy++) {
        __syncthreads();
        const uint4* srcA = (const uint4*)(nhwc +
            ((size_t)(b * Hp + y + dy) * Wp + x0) * 64);
        for (int i = tid; i < (TW + 4) * 8; i += NW * 32) {
            int p = i >> 3, g = i & 7;
            *(uint4*)(As + p * 128 + ((g ^ (p & 7)) << 4)) = srcA[i];
        }
        // B: 5 taps x 64 k-rows x 64B, granule swizzle g ^ ((k>>1)&3)
        const uint4* srcB = (const uint4*)(wh + (size_t)dy * 5 * 2048);
        for (int i = tid; i < 1280; i += NW * 32) {
            int tap5 = i >> 8, r = i & 255, k = r >> 2, g = r & 3;
            *(uint4*)(Bs + tap5 * 4096 + k * 64 + ((g ^ ((k >> 1) & 3)) << 4)) = srcB[i];
        }
        __syncthreads();

#pragma unroll
        for (int dx = 0; dx < 5; dx++) {
#pragma unroll
            for (int ks = 0; ks < 4; ks++) {
                uint32_t a[4][4];
#pragma unroll
                for (int mh = 0; mh < 4; mh++) {
                    int r = warp * 64 + mh * 16 + dx + (lane & 15);
                    int g = ks * 2 + (lane >> 4);
                    uint32_t addr = As_b + r * 128 + ((g ^ (r & 7)) << 4);
                    asm volatile(
                        "ldmatrix.sync.aligned.m8n8.x4.shared.b16 {%0,%1,%2,%3}, [%4];"
                        : "=r"(a[mh][0]), "=r"(a[mh][1]), "=r"(a[mh][2]), "=r"(a[mh][3])
                        : "r"(addr));
                }
#pragma unroll
                for (int j2 = 0; j2 < 2; j2++) {
                    uint32_t b0, b1, b2, b3;
                    {
                        int k = ks * 16 + (lane & 15);
                        int g = j2 * 2 + (lane >> 4);
                        uint32_t addr = Bs_b + dx * 4096 + k * 64
                                      + ((g ^ ((k >> 1) & 3)) << 4);
                        asm volatile(
                            "ldmatrix.sync.aligned.m8n8.x4.trans.shared.b16 {%0,%1,%2,%3}, [%4];"
                            : "=r"(b0), "=r"(b1), "=r"(b2), "=r"(b3) : "r"(addr));
                    }
#pragma unroll
                    for (int mh = 0; mh < 4; mh++) {
                        float* d0 = acc[mh][j2 * 2 + 0];
                        asm volatile(
                            "mma.sync.aligned.m16n8k16.row.col.f32.f16.f16.f32 "
                            "{%0,%1,%2,%3}, {%4,%5,%6,%7}, {%8,%9}, {%0,%1,%2,%3};"
                            : "+f"(d0[0]), "+f"(d0[1]), "+f"(d0[2]), "+f"(d0[3])
                            : "r"(a[mh][0]), "r"(a[mh][1]), "r"(a[mh][2]), "r"(a[mh][3]),
                              "r"(b0), "r"(b1));
                        float* d1 = acc[mh][j2 * 2 + 1];
                        asm volatile(
                            "mma.sync.aligned.m16n8k16.row.col.f32.f16.f16.f32 "
                            "{%0,%1,%2,%3}, {%4,%5,%6,%7}, {%8,%9}, {%0,%1,%2,%3};"
                            : "+f"(d1[0]), "+f"(d1[1]), "+f"(d1[2]), "+f"(d1[3])
                            : "r"(a[mh][0]), "r"(a[mh][1]), "r"(a[mh][2]), "r"(a[mh][3]),
                              "r"(b2), "r"(b3));
                    }
                }
            }
        }
    }

    int r0 = lane >> 2, c0 = (lane & 3) * 2;
#pragma unroll
    for (int mh = 0; mh < 4; mh++) {
        int xbase = x0 + warp * 64 + mh * 16;
#pragma unroll
        for (int j = 0; j < 4; j++) {
            int oc0 = j * 8 + c0;
            float bs0 = __ldg(&bias[oc0]), bs1 = __ldg(&bias[oc0 + 1]);
            size_t p0 = (((size_t)b * 32 + oc0)     * H + y) * W;
            size_t p1 = (((size_t)b * 32 + oc0 + 1) * H + y) * W;
            out[p0 + xbase + r0]     = fmaxf(acc[mh][j][0] + bs0, 0.0f);
            out[p1 + xbase + r0]     = fmaxf(acc[mh][j][1] + bs1, 0.0f);
            out[p0 + xbase + r0 + 8] = fmaxf(acc[mh][j][2] + bs0, 0.0f);
            out[p1 + xbase + r0 + 8] = fmaxf(acc[mh][j][3] + bs1, 0.0f);
        }
    }
}

// ---------------------------------------------------------------------------
// conv3: 5x5, IC=32 -> OC=1. 128x8 px tile, 4 px/thread (proven R8 version).
// ---------------------------------------------------------------------------
__global__ __launch_bounds__(256)
void conv3_kernel(const float* __restrict__ in, const float* __restrict__ w,
                  const float* __restrict__ bias, float* __restrict__ out,
                  int H, int W)
{
    const int ICC = 4, IC = 32;
    __shared__ __align__(16) float in_s[ICC][12][132];
    __shared__ float w_s[IC][25];

    int b  = blockIdx.z;
    int x0 = blockIdx.x * 128;
    int y0 = blockIdx.y * 8;
    int tid = threadIdx.x;
    int sx = tid & 31, sy = tid >> 5;

    for (int t = tid; t < IC * 25; t += 256) w_s[t / 25][t % 25] = w[t];

    float acc[4] = {0.f, 0.f, 0.f, 0.f};
    for (int cc = 0; cc < IC; cc += ICC) {
        __syncthreads();
        for (int t = tid; t < ICC * 12 * 132; t += 256) {
            int ic  = t / (12 * 132);
            int rem = t - ic * (12 * 132);
            int r = rem / 132, c = rem - r * 132;
            int gy = y0 - 2 + r, gx = x0 - 2 + c;
            float v = 0.f;
            if (gy >= 0 && gy < H && gx >= 0 && gx < W)
                v = in[((size_t)(b * IC + cc + ic) * H + gy) * W + gx];
            in_s[ic][r][c] = v;
        }
        __syncthreads();
#pragma unroll
        for (int ic = 0; ic < ICC; ic++) {
#pragma unroll
            for (int dy = 0; dy < 5; dy++) {
                const float* row = &in_s[ic][sy + dy][sx * 4];
                float4 Av = *(const float4*)row;
                float4 Bv = *(const float4*)(row + 4);
                float c8 = row[8];
                float v[9] = {Av.x, Av.y, Av.z, Av.w, Bv.x, Bv.y, Bv.z, Bv.w, c8};
                const float* wr = &w_s[cc + ic][dy * 5];
#pragma unroll
                for (int dx = 0; dx < 5; dx++) {
                    float wv = wr[dx];
#pragma unroll
                    for (int q = 0; q < 4; q++)
                        acc[q] = fmaf(v[dx + q], wv, acc[q]);
                }
            }
        }
    }

    int yy = y0 + sy;
    if (yy < H) {
#pragma unroll
        for (int q = 0; q < 4; q++) {
            int xx = x0 + sx * 4 + q;
            if (xx < W)
                out[((size_t)b * H + yy) * W + xx] = acc[q] + bias[0];
        }
    }
}

// ---------------------------------------------------------------------------
// Orchestration
// ---------------------------------------------------------------------------
extern "C" void kernel_launch(void* const* d_in, const int* in_sizes, int n_in,
                              void* d_out, int out_size)
{
    const float* x        = (const float*)d_in[0];
    const float* elev0    = (const float*)d_in[1];
    const float* elev1    = (const float*)d_in[2];
    const int*   psi_idx1 = (const int*)  d_in[3];
    const float* psi_val1 = (const float*)d_in[4];
    const float* w1       = (const float*)d_in[5];
    const float* b1       = (const float*)d_in[6];
    const float* cw2_1    = (const float*)d_in[7];
    const float* cb2_1    = (const float*)d_in[8];
    const float* cw3_1    = (const float*)d_in[9];
    const float* cb3_1    = (const float*)d_in[10];
    const int*   psi_idx2 = (const int*)  d_in[11];
    const float* psi_val2 = (const float*)d_in[12];
    const float* w2       = (const float*)d_in[13];
    const float* b2       = (const float*)d_in[14];
    const float* cw2_2    = (const float*)d_in[15];
    const float* cb2_2    = (const float*)d_in[16];
    const float* cw3_2    = (const float*)d_in[17];
    const float* cb3_2    = (const float*)d_in[18];
    float* out = (float*)d_out;

    float* scratch = nullptr;
    cudaGetSymbolAddress((void**)&scratch, g_scratch);
    __half* nhwcH = (__half*)(scratch + OFF_NHWCH);
    float*  bufB2 = scratch + OFF_B2;
    float*  bufH  = scratch + OFF_H;
    float*  bufY1 = scratch + OFF_Y1;
    __half* bufWH = (__half*)(scratch + OFF_WH);
    __half* bufWQ = (__half*)(scratch + OFF_WQ);

    const int SMEM2 = (128 + 4) * 128 + 20480;   // 37376
    const int SMEM4 = (256 + 4) * 128 + 20480;   // 53760
    cudaFuncSetAttribute(conv2_mma<2>, cudaFuncAttributeMaxDynamicSharedMemorySize, SMEM2);
    cudaFuncSetAttribute(conv2_mma<4>, cudaFuncAttributeMaxDynamicSharedMemorySize, SMEM4);

    // ---------------- stage 1: 90x180 -> 180x360 ----------------
    {
        const int H = 180, W = 360, P = H * W, Hp = H + 4, Wp = W + 4;
        int total = B_ * H * W;
        int nbMain = (P + 127) / 128;
        int perB = 4 * Wp + (Hp - 4) * 4;
        int nbBorder = (B_ * perB + 127) / 128;
        upsample_concat_kernel<<<(total + 255) / 256, 256>>>(x, elev0, bufH, 90, 180);
        wq_transform<<<8, 256>>>(w1, bufWQ);
        disco_mma<<<nbMain + nbBorder, 128>>>(bufH, psi_idx1, psi_val1, bufWQ, b1,
                                              nhwcH, P, W, Hp, Wp, nbMain);
        wtransform_kernel<<<200, 256>>>(cw2_1, bufWH);
        dim3 g2((W + 127) / 128, H, B_);
        conv2_mma<2><<<g2, 64, SMEM2>>>(nhwcH, bufWH, cb2_1, bufB2, H, W);
        dim3 g3((W + 127) / 128, (H + 7) / 8, B_);
        conv3_kernel<<<g3, 256>>>(bufB2, cw3_1, cb3_1, bufY1, H, W);
    }
    // ---------------- stage 2: 180x360 -> 360x720 ----------------
    {
        const int H = 360, W = 720, P = H * W, Hp = H + 4, Wp = W + 4;
        int total = B_ * H * W;
        int nbMain = (P + 127) / 128;
        int perB = 4 * Wp + (Hp - 4) * 4;
        int nbBorder = (B_ * perB + 127) / 128;
        upsample_concat_kernel<<<(total + 255) / 256, 256>>>(bufY1, elev1, bufH, 180, 360);
        wq_transform<<<8, 256>>>(w2, bufWQ);
        disco_mma<<<nbMain + nbBorder, 128>>>(bufH, psi_idx2, psi_val2, bufWQ, b2,
                                              nhwcH, P, W, Hp, Wp, nbMain);
        wtransform_kernel<<<200, 256>>>(cw2_2, bufWH);
        dim3 g2((W + 255) / 256, H, B_);
        conv2_mma<4><<<g2, 128, SMEM4>>>(nhwcH, bufWH, cb2_2, bufB2, H, W);
        dim3 g3((W + 127) / 128, (H + 7) / 8, B_);
        conv3_kernel<<<g3, 256>>>(bufB2, cw3_2, cb3_2, out, H, W);
    }
}